// round 12
// baseline (speedup 1.0000x reference)
#include <cuda_runtime.h>
#include <cuda_bf16.h>
#include <math.h>
#include <stdint.h>

#define W_WIN 4096
#define KTOK  32
#define CDIM  256
#define HEADS 8
#define DHEAD 32
#define NTOK  (W_WIN * KTOK)
#define KC    27
#define SDIM  33
#define RTOT  (W_WIN * SDIM)
#define EPS   1e-5f

// ---------------- device scratch ----------------
__device__ float g_x [(size_t)RTOT * CDIM];                 // residual 1 (fp32)
__device__ float g_x2[(size_t)RTOT * CDIM];                 // residual 2 (fp32)
__device__ __nv_bfloat16 g_h   [(size_t)RTOT * CDIM];       // LN1 out
__device__ __nv_bfloat16 g_h2  [(size_t)RTOT * CDIM];       // LN2 out
__device__ __nv_bfloat16 g_qkv [(size_t)RTOT * 3 * CDIM];   // qkv
__device__ __nv_bfloat16 g_attn[(size_t)RTOT * CDIM];       // attn out
__device__ __nv_bfloat16 g_f1  [(size_t)RTOT * 1024];       // gelu(fc1)
__device__ __nv_bfloat16 g_wq[768 * 256];
__device__ __nv_bfloat16 g_wp[256 * 256];
__device__ __nv_bfloat16 g_w1[1024 * 256];
__device__ __nv_bfloat16 g_w2[256 * 1024];

// ---------------- helpers ----------------
__device__ __forceinline__ uint32_t smem_u32(const void* p) {
    uint32_t a;
    asm("{ .reg .u64 t; cvta.to.shared.u64 t, %1; cvt.u32.u64 %0, t; }"
        : "=r"(a) : "l"(p));
    return a;
}
__device__ __forceinline__ void cp16(uint32_t dst, const void* src) {
    asm volatile("cp.async.ca.shared.global [%0], [%1], 16;" :: "r"(dst), "l"(src));
}
#define CP_COMMIT() asm volatile("cp.async.commit_group;" ::: "memory")
#define CP_WAIT(n)  asm volatile("cp.async.wait_group %0;" :: "n"(n) : "memory")

__device__ __forceinline__ void mma_bf16(float d[4], uint32_t a0, uint32_t a1,
                                         uint32_t a2, uint32_t a3,
                                         uint32_t b0, uint32_t b1) {
    asm volatile(
        "mma.sync.aligned.m16n8k16.row.col.f32.bf16.bf16.f32 "
        "{%0,%1,%2,%3}, {%4,%5,%6,%7}, {%8,%9}, {%0,%1,%2,%3};"
        : "+f"(d[0]), "+f"(d[1]), "+f"(d[2]), "+f"(d[3])
        : "r"(a0), "r"(a1), "r"(a2), "r"(a3), "r"(b0), "r"(b1));
}
__device__ __forceinline__ void ldsm_x4(uint32_t& r0, uint32_t& r1,
                                        uint32_t& r2, uint32_t& r3, uint32_t a) {
    asm volatile("ldmatrix.sync.aligned.m8n8.x4.shared.b16 {%0,%1,%2,%3}, [%4];"
                 : "=r"(r0), "=r"(r1), "=r"(r2), "=r"(r3) : "r"(a));
}
__device__ __forceinline__ float bflo(uint32_t u) { return __uint_as_float(u << 16); }
__device__ __forceinline__ float bfhi(uint32_t u) { return __uint_as_float(u & 0xffff0000u); }

// ---------------- fused weight transpose -> bf16 (all four) ----------------
__global__ void transpose_all_kernel(
    const float* __restrict__ qkv_w, const float* __restrict__ proj_w,
    const float* __restrict__ fc1_w, const float* __restrict__ fc2_w)
{
    int i = blockIdx.x * 256 + threadIdx.x;
    if (i < 196608) {
        int n = i / 256, k = i - n * 256;           // Kd=256, Nd=768
        g_wq[i] = __float2bfloat16(qkv_w[(size_t)k * 768 + n]);
    } else if (i < 262144) {
        int j = i - 196608;
        int n = j / 256, k = j - n * 256;           // 256x256
        g_wp[j] = __float2bfloat16(proj_w[(size_t)k * 256 + n]);
    } else if (i < 524288) {
        int j = i - 262144;
        int n = j / 256, k = j - n * 256;           // Kd=256, Nd=1024
        g_w1[j] = __float2bfloat16(fc1_w[(size_t)k * 1024 + n]);
    } else {
        int j = i - 524288;
        int n = j / 1024, k = j - n * 1024;         // Kd=1024, Nd=256
        g_w2[j] = __float2bfloat16(fc2_w[(size_t)k * 256 + n]);
    }
}

// ---------------- fused CPE + build x + LN1 (float4 gather) ----------------
__global__ void __launch_bounds__(256) cpe_ln1_kernel(
    const float* __restrict__ data, const float* __restrict__ relay,
    const int* __restrict__ neigh, const float* __restrict__ cpe_w,
    const float* __restrict__ bn_gamma, const float* __restrict__ bn_beta,
    const float* __restrict__ bn_mean, const float* __restrict__ bn_var,
    const float* __restrict__ g, const float* __restrict__ b)
{
    int warp = threadIdx.x >> 5, lane = threadIdx.x & 31;
    int gr = blockIdx.x * 8 + warp;
    int w = gr / SDIM, s = gr - w * SDIM;

    float4 v[2];
    if (s == 0) {
        const float4* src = (const float4*)(relay + (size_t)w * CDIM);
        #pragma unroll
        for (int i = 0; i < 2; i++) v[i] = src[lane + i * 32];
    } else {
        int n = w * KTOK + s - 1;
        int nb = (lane < KC) ? neigh[(size_t)n * KC + lane] : 0;
        float4 acc[2];
        #pragma unroll
        for (int i = 0; i < 2; i++) acc[i] = make_float4(0.f, 0.f, 0.f, 0.f);
        #pragma unroll
        for (int k = 0; k < KC; k++) {
            int idx = __shfl_sync(0xffffffffu, nb, k);
            const float4* drow = (const float4*)(data + (size_t)idx * CDIM);
            const float4* wrow = (const float4*)(cpe_w + k * CDIM);
            #pragma unroll
            for (int i = 0; i < 2; i++) {
                float4 d = drow[lane + i * 32], ww = wrow[lane + i * 32];
                acc[i].x = fmaf(d.x, ww.x, acc[i].x);
                acc[i].y = fmaf(d.y, ww.y, acc[i].y);
                acc[i].z = fmaf(d.z, ww.z, acc[i].z);
                acc[i].w = fmaf(d.w, ww.w, acc[i].w);
            }
        }
        const float4* drow = (const float4*)(data + (size_t)n * CDIM);
        const float4* bm = (const float4*)bn_mean;
        const float4* bv = (const float4*)bn_var;
        const float4* bg = (const float4*)bn_gamma;
        const float4* bb = (const float4*)bn_beta;
        #pragma unroll
        for (int i = 0; i < 2; i++) {
            int c = lane + i * 32;
            float4 d = drow[c], m = bm[c], va = bv[c], ga = bg[c], be = bb[c];
            v[i].x = d.x + (acc[i].x - m.x) * rsqrtf(va.x + EPS) * ga.x + be.x;
            v[i].y = d.y + (acc[i].y - m.y) * rsqrtf(va.y + EPS) * ga.y + be.y;
            v[i].z = d.z + (acc[i].z - m.z) * rsqrtf(va.z + EPS) * ga.z + be.z;
            v[i].w = d.w + (acc[i].w - m.w) * rsqrtf(va.w + EPS) * ga.w + be.w;
        }
    }

    float sm = 0.f, s2 = 0.f;
    #pragma unroll
    for (int i = 0; i < 2; i++) {
        sm += v[i].x + v[i].y + v[i].z + v[i].w;
        s2 = fmaf(v[i].x, v[i].x, s2); s2 = fmaf(v[i].y, v[i].y, s2);
        s2 = fmaf(v[i].z, v[i].z, s2); s2 = fmaf(v[i].w, v[i].w, s2);
    }
    #pragma unroll
    for (int o = 16; o; o >>= 1) {
        sm += __shfl_xor_sync(0xffffffffu, sm, o);
        s2 += __shfl_xor_sync(0xffffffffu, s2, o);
    }
    float mu = sm * (1.f / CDIM);
    float rs = rsqrtf(s2 * (1.f / CDIM) - mu * mu + EPS);
    float4* xo = (float4*)(g_x + (size_t)gr * CDIM);
    uint32_t* ho = (uint32_t*)(g_h + (size_t)gr * CDIM);
    const float4* gg = (const float4*)g;
    const float4* gb = (const float4*)b;
    #pragma unroll
    for (int i = 0; i < 2; i++) {
        int c = lane + i * 32;
        xo[c] = v[i];
        float4 ga = gg[c], be = gb[c];
        __nv_bfloat162 h0 = __floats2bfloat162_rn(
            (v[i].x - mu) * rs * ga.x + be.x,
            (v[i].y - mu) * rs * ga.y + be.y);
        __nv_bfloat162 h1 = __floats2bfloat162_rn(
            (v[i].z - mu) * rs * ga.z + be.z,
            (v[i].w - mu) * rs * ga.w + be.w);
        uint2 pk;
        pk.x = *(uint32_t*)&h0;
        pk.y = *(uint32_t*)&h1;
        *(uint2*)(ho + 2 * c) = pk;
    }
}

// ---------------- LN2: g_x2 (fp32) -> g_h2 (bf16) ----------------
__global__ void __launch_bounds__(256) ln2_kernel(
    const float* __restrict__ g, const float* __restrict__ b)
{
    int warp = threadIdx.x >> 5, lane = threadIdx.x & 31;
    int gr = blockIdx.x * 8 + warp;
    const float2* src = (const float2*)(g_x2 + (size_t)gr * CDIM);
    float2 v[4];
    float sm = 0.f, s2 = 0.f;
    #pragma unroll
    for (int i = 0; i < 4; i++) {
        v[i] = src[lane + i * 32];
        sm += v[i].x + v[i].y;
        s2 = fmaf(v[i].x, v[i].x, fmaf(v[i].y, v[i].y, s2));
    }
    #pragma unroll
    for (int o = 16; o; o >>= 1) {
        sm += __shfl_xor_sync(0xffffffffu, sm, o);
        s2 += __shfl_xor_sync(0xffffffffu, s2, o);
    }
    float mu = sm * (1.f / CDIM);
    float rs = rsqrtf(s2 * (1.f / CDIM) - mu * mu + EPS);
    uint32_t* ho = (uint32_t*)(g_h2 + (size_t)gr * CDIM);
    const float2* gg = (const float2*)g;
    const float2* gb = (const float2*)b;
    #pragma unroll
    for (int i = 0; i < 4; i++) {
        int c = lane + i * 32;
        float2 ga = gg[c], be = gb[c];
        __nv_bfloat162 h = __floats2bfloat162_rn(
            (v[i].x - mu) * rs * ga.x + be.x,
            (v[i].y - mu) * rs * ga.y + be.y);
        ho[c] = *(uint32_t*)&h;
    }
}

// ---------------- attention v5: single-pass, fp32 K/V in smem ----------------
// block = window, 288 threads (264 active: one per (head, query)).
// smem: K/V fp32 [33][520] (K cols 0..255, V 256..511, 8 pad).
// Single sweep: e = exp(dot), accumulate e*V, normalize at end.
// fp32 K/V: 16 LDS.128 + 64 FMA per key (no per-iteration unpack ALU).
#define KVW 520
#define ATTN_SMEM (SDIM * KVW * 4)                   /* 68640 B */

__global__ void __launch_bounds__(288) attn_kernel()
{
    extern __shared__ float skv[];                   // [33][520]
    int w = blockIdx.x, tid = threadIdx.x;

    // fill: bf16 -> fp32 unpack once
    const uint4* src4 = (const uint4*)(g_qkv + (size_t)w * SDIM * 768);
    for (int i = tid; i < SDIM * 64; i += 288) {
        int r = i >> 6, c = i & 63;
        uint4 q4 = src4[r * 96 + 32 + c];
        float* dst = skv + r * KVW + c * 8;
        float4 f0 = make_float4(bflo(q4.x), bfhi(q4.x), bflo(q4.y), bfhi(q4.y));
        float4 f1 = make_float4(bflo(q4.z), bfhi(q4.z), bflo(q4.w), bfhi(q4.w));
        *(float4*)(dst)     = f0;
        *(float4*)(dst + 4) = f1;
    }
    __syncthreads();

    if (tid < HEADS * SDIM) {
        int h = tid / SDIM, s = tid - h * SDIM;
        const float scale = 0.17677669529663687f;

        float q[DHEAD];
        {
            const uint32_t* qsrc = (const uint32_t*)(
                g_qkv + ((size_t)w * SDIM + s) * 768) + h * 16;
            #pragma unroll
            for (int i = 0; i < 16; i++) {
                uint32_t p = qsrc[i];
                q[2 * i]     = bflo(p) * scale;
                q[2 * i + 1] = bfhi(p) * scale;
            }
        }

        float o[DHEAD];
        #pragma unroll
        for (int d = 0; d < DHEAD; d++) o[d] = 0.f;
        float ssum = 0.f;

        #pragma unroll 1
        for (int t = 0; t < SDIM; t++) {
            const float4* kr = (const float4*)(skv + t * KVW + h * DHEAD);
            float dot = 0.f;
            #pragma unroll
            for (int j = 0; j < 8; j++) {
                float4 kk = kr[j];
                dot = fmaf(q[4 * j],     kk.x, dot);
                dot = fmaf(q[4 * j + 1], kk.y, dot);
                dot = fmaf(q[4 * j + 2], kk.z, dot);
                dot = fmaf(q[4 * j + 3], kk.w, dot);
            }
            float e = __expf(dot);
            ssum += e;
            const float4* vr = (const float4*)(skv + t * KVW + 256 + h * DHEAD);
            #pragma unroll
            for (int j = 0; j < 8; j++) {
                float4 vv = vr[j];
                o[4 * j]     = fmaf(e, vv.x, o[4 * j]);
                o[4 * j + 1] = fmaf(e, vv.y, o[4 * j + 1]);
                o[4 * j + 2] = fmaf(e, vv.z, o[4 * j + 2]);
                o[4 * j + 3] = fmaf(e, vv.w, o[4 * j + 3]);
            }
        }
        float inv = 1.f / ssum;
        __nv_bfloat162* dst = (__nv_bfloat162*)(
            g_attn + ((size_t)w * SDIM + s) * CDIM + h * DHEAD);
        #pragma unroll
        for (int i = 0; i < 16; i++)
            dst[i] = __floats2bfloat162_rn(o[2 * i] * inv, o[2 * i + 1] * inv);
    }
}

// ---------------- bf16 mma.sync GEMM (m16n8k16, ldmatrix operands) ----------------
#define CHUNK_K 64
#define SBF     72
#define SBF_B   (SBF * 2)
#define BUF_ELE (256 * SBF)
#define BUF_BYTES (BUF_ELE * 2)
#define GEMM_SMEM (2 * BUF_BYTES)

template<int KT, int NT, int EPI>
__global__ void __launch_bounds__(256) gemm_mma(
    const __nv_bfloat16* __restrict__ A, const __nv_bfloat16* __restrict__ B,
    const float* __restrict__ bias, const float* __restrict__ res,
    void* __restrict__ outp)
{
    extern __shared__ float smemf[];
    __nv_bfloat16* smem = (__nv_bfloat16*)smemf;
    const int tid = threadIdx.x;
    const int wid = tid >> 5, lane = tid & 31;
    const int g = lane >> 2, t = lane & 3;
    const int warp_m = wid & 1, warp_n = wid >> 1;
    const int n0 = blockIdx.x * 128;
    const int m0 = blockIdx.y * 128;
    const uint32_t sbase = smem_u32(smem);

    const int lm = lane >> 3;
    const int lr = lane & 7;
    const uint32_t a_off0 = (uint32_t)(warp_m * 64 + (lm & 1) * 8 + lr) * SBF_B
                          + (uint32_t)(lm >> 1) * 16;
    const uint32_t b_off0 = (uint32_t)(128 * SBF_B)
                          + (uint32_t)(warp_n * 32 + (lm >> 1) * 8 + lr) * SBF_B
                          + (uint32_t)(lm & 1) * 16;

    float acc[4][4][4];
    #pragma unroll
    for (int i = 0; i < 4; i++)
        #pragma unroll
        for (int j = 0; j < 4; j++)
            #pragma unroll
            for (int r = 0; r < 4; r++) acc[i][j][r] = 0.f;

    constexpr int KCH = KT / CHUNK_K;

    auto load_chunk = [&](int s, int kc) {
        uint32_t base = sbase + (uint32_t)s * BUF_BYTES;
        #pragma unroll
        for (int it = 0; it < 4; it++) {
            int idx = it * 256 + tid;
            int row = idx >> 3, seg = idx & 7;
            cp16(base + (uint32_t)(row * SBF_B + seg * 16),
                 A + (size_t)(m0 + row) * KT + kc * CHUNK_K + seg * 8);
        }
        #pragma unroll
        for (int it = 0; it < 4; it++) {
            int idx = it * 256 + tid;
            int row = idx >> 3, seg = idx & 7;
            cp16(base + (uint32_t)(128 * SBF_B + row * SBF_B + seg * 16),
                 B + (size_t)(n0 + row) * KT + kc * CHUNK_K + seg * 8);
        }
    };

    load_chunk(0, 0); CP_COMMIT();

    for (int kc = 0; kc < KCH; kc++) {
        int s = kc & 1;
        if (kc + 1 < KCH) {
            load_chunk((kc + 1) & 1, kc + 1); CP_COMMIT();
            CP_WAIT(1);
        } else {
            CP_WAIT(0);
        }
        __syncthreads();

        uint32_t abase = sbase + (uint32_t)s * BUF_BYTES + a_off0;
        uint32_t bbase = sbase + (uint32_t)s * BUF_BYTES + b_off0;

        #pragma unroll
        for (int ks = 0; ks < 4; ks++) {
            uint32_t kb = (uint32_t)ks * 32;
            uint32_t bf[4][2];
            ldsm_x4(bf[0][0], bf[0][1], bf[1][0], bf[1][1], bbase + kb);
            ldsm_x4(bf[2][0], bf[2][1], bf[3][0], bf[3][1],
                    bbase + kb + 16u * SBF_B);
            #pragma unroll
            for (int mt = 0; mt < 4; mt++) {
                uint32_t a0, a1, a2, a3;
                ldsm_x4(a0, a1, a2, a3, abase + kb + (uint32_t)mt * 16u * SBF_B);
                #pragma unroll
                for (int nt = 0; nt < 4; nt++)
                    mma_bf16(acc[mt][nt], a0, a1, a2, a3, bf[nt][0], bf[nt][1]);
            }
        }
        __syncthreads();
    }

    float* stg = smemf;
    #pragma unroll
    for (int mt = 0; mt < 4; mt++) {
        #pragma unroll
        for (int nt = 0; nt < 4; nt++) {
            int row = warp_m * 64 + mt * 16 + g;
            int col = warp_n * 32 + nt * 8 + 2 * t;
            stg[row * 132 + col]           = acc[mt][nt][0];
            stg[row * 132 + col + 1]       = acc[mt][nt][1];
            stg[(row + 8) * 132 + col]     = acc[mt][nt][2];
            stg[(row + 8) * 132 + col + 1] = acc[mt][nt][3];
        }
    }
    __syncthreads();

    if (EPI == 0 || EPI == 2) {
        int cp = tid & 63;
        int rb = tid >> 6;
        float b0 = bias[n0 + 2 * cp], b1 = bias[n0 + 2 * cp + 1];
        uint32_t* ob = (uint32_t*)outp;
        #pragma unroll 4
        for (int i = 0; i < 32; i++) {
            int r = rb + i * 4;
            int gr = m0 + r;
            float v0 = stg[r * 132 + 2 * cp] + b0;
            float v1 = stg[r * 132 + 2 * cp + 1] + b1;
            if (EPI == 2) {
                float x3 = v0 * v0 * v0;
                float th = tanhf(0.7978845608028654f * (v0 + 0.044715f * x3));
                v0 = 0.5f * v0 * (1.f + th);
                x3 = v1 * v1 * v1;
                th = tanhf(0.7978845608028654f * (v1 + 0.044715f * x3));
                v1 = 0.5f * v1 * (1.f + th);
            }
            __nv_bfloat162 pk = __floats2bfloat162_rn(v0, v1);
            ob[((size_t)gr * NT + n0) / 2 + cp] = *(uint32_t*)&pk;
        }
    } else {
        int col = tid & 127;
        int r0  = tid >> 7;
        float bi = bias[n0 + col];
        float* of = (float*)outp;
        #pragma unroll 4
        for (int i = 0; i < 64; i++) {
            int r = r0 + i * 2;
            int gr = m0 + r;
            float v = stg[r * 132 + col] + bi + res[(size_t)gr * NT + n0 + col];
            if (EPI == 3) {
                int w = gr / SDIM, sx = gr - (gr / SDIM) * SDIM;
                size_t dst = (sx == 0)
                    ? ((size_t)NTOK * CDIM + (size_t)w * CDIM + n0 + col)
                    : (((size_t)(w * KTOK + sx - 1)) * CDIM + n0 + col);
                of[dst] = v;
            } else {
                of[(size_t)gr * NT + n0 + col] = v;
            }
        }
    }
}

// ---------------------------------------------------------------------------
extern "C" void kernel_launch(void* const* d_in, const int* in_sizes, int n_in,
                              void* d_out, int out_size)
{
    const float* data     = (const float*)d_in[0];
    const float* relay    = (const float*)d_in[1];
    const int*   neigh    = (const int*)  d_in[2];
    const float* cpe_w    = (const float*)d_in[3];
    const float* bn_gamma = (const float*)d_in[4];
    const float* bn_beta  = (const float*)d_in[5];
    const float* bn_mean  = (const float*)d_in[6];
    const float* bn_var   = (const float*)d_in[7];
    const float* norm1_g  = (const float*)d_in[8];
    const float* norm1_b  = (const float*)d_in[9];
    const float* qkv_w    = (const float*)d_in[10];
    const float* qkv_b    = (const float*)d_in[11];
    const float* proj_w   = (const float*)d_in[12];
    const float* proj_b   = (const float*)d_in[13];
    const float* norm2_g  = (const float*)d_in[14];
    const float* norm2_b  = (const float*)d_in[15];
    const float* fc1_w    = (const float*)d_in[16];
    const float* fc1_b    = (const float*)d_in[17];
    const float* fc2_w    = (const float*)d_in[18];
    const float* fc2_b    = (const float*)d_in[19];
    float* out = (float*)d_out;

    static bool inited = false;
    static __nv_bfloat16 *p_h, *p_h2, *p_qkv, *p_attn, *p_f1;
    static __nv_bfloat16 *p_wq, *p_wp, *p_w1, *p_w2;
    static float *p_x, *p_x2;
    if (!inited) {
        cudaFuncSetAttribute(gemm_mma<256, 768, 0>,
            cudaFuncAttributeMaxDynamicSharedMemorySize, GEMM_SMEM);
        cudaFuncSetAttribute(gemm_mma<256, 256, 1>,
            cudaFuncAttributeMaxDynamicSharedMemorySize, GEMM_SMEM);
        cudaFuncSetAttribute(gemm_mma<256, 1024, 2>,
            cudaFuncAttributeMaxDynamicSharedMemorySize, GEMM_SMEM);
        cudaFuncSetAttribute(gemm_mma<1024, 256, 3>,
            cudaFuncAttributeMaxDynamicSharedMemorySize, GEMM_SMEM);
        cudaFuncSetAttribute(attn_kernel,
            cudaFuncAttributeMaxDynamicSharedMemorySize, ATTN_SMEM);
        void* t;
        cudaGetSymbolAddress(&t, g_h);    p_h    = (__nv_bfloat16*)t;
        cudaGetSymbolAddress(&t, g_h2);   p_h2   = (__nv_bfloat16*)t;
        cudaGetSymbolAddress(&t, g_qkv);  p_qkv  = (__nv_bfloat16*)t;
        cudaGetSymbolAddress(&t, g_attn); p_attn = (__nv_bfloat16*)t;
        cudaGetSymbolAddress(&t, g_f1);   p_f1   = (__nv_bfloat16*)t;
        cudaGetSymbolAddress(&t, g_x);    p_x    = (float*)t;
        cudaGetSymbolAddress(&t, g_x2);   p_x2   = (float*)t;
        cudaGetSymbolAddress(&t, g_wq);   p_wq   = (__nv_bfloat16*)t;
        cudaGetSymbolAddress(&t, g_wp);   p_wp   = (__nv_bfloat16*)t;
        cudaGetSymbolAddress(&t, g_w1);   p_w1   = (__nv_bfloat16*)t;
        cudaGetSymbolAddress(&t, g_w2);   p_w2   = (__nv_bfloat16*)t;
        inited = true;
    }

    transpose_all_kernel<<<786432 / 256, 256>>>(qkv_w, proj_w, fc1_w, fc2_w);

    cpe_ln1_kernel<<<RTOT / 8, 256>>>(data, relay, neigh, cpe_w,
                                      bn_gamma, bn_beta, bn_mean, bn_var,
                                      norm1_g, norm1_b);

    const int GB = RTOT / 128;  // 1056
    gemm_mma<256, 768, 0><<<dim3(6, GB), 256, GEMM_SMEM>>>(p_h, p_wq, qkv_b, nullptr, p_qkv);

    attn_kernel<<<W_WIN, 288, ATTN_SMEM>>>();

    gemm_mma<256, 256, 1><<<dim3(2, GB), 256, GEMM_SMEM>>>(p_attn, p_wp, proj_b, p_x, p_x2);

    ln2_kernel<<<RTOT / 8, 256>>>(norm2_g, norm2_b);

    gemm_mma<256, 1024, 2><<<dim3(8, GB), 256, GEMM_SMEM>>>(p_h2, p_w1, fc1_b, nullptr, p_f1);

    gemm_mma<1024, 256, 3><<<dim3(2, GB), 256, GEMM_SMEM>>>(p_f1, p_w2, fc2_b, p_x2, out);
}

// round 13
// speedup vs baseline: 1.1314x; 1.1314x over previous
#include <cuda_runtime.h>
#include <cuda_bf16.h>
#include <math.h>
#include <stdint.h>

#define W_WIN 4096
#define KTOK  32
#define CDIM  256
#define HEADS 8
#define DHEAD 32
#define NTOK  (W_WIN * KTOK)
#define KC    27
#define SDIM  33
#define RTOT  (W_WIN * SDIM)
#define EPS   1e-5f

// ---------------- device scratch ----------------
__device__ float g_x [(size_t)RTOT * CDIM];                 // residual 1 (fp32)
__device__ float g_x2[(size_t)RTOT * CDIM];                 // residual 2 (fp32)
__device__ __nv_bfloat16 g_h   [(size_t)RTOT * CDIM];       // LN1 out
__device__ __nv_bfloat16 g_h2  [(size_t)RTOT * CDIM];       // LN2 out
__device__ __nv_bfloat16 g_qkv [(size_t)RTOT * 3 * CDIM];   // qkv
__device__ __nv_bfloat16 g_attn[(size_t)RTOT * CDIM];       // attn out
__device__ __nv_bfloat16 g_f1  [(size_t)RTOT * 1024];       // gelu(fc1)
__device__ __nv_bfloat16 g_wq[768 * 256];
__device__ __nv_bfloat16 g_wp[256 * 256];
__device__ __nv_bfloat16 g_w1[1024 * 256];
__device__ __nv_bfloat16 g_w2[256 * 1024];

// ---------------- helpers ----------------
__device__ __forceinline__ uint32_t smem_u32(const void* p) {
    uint32_t a;
    asm("{ .reg .u64 t; cvta.to.shared.u64 t, %1; cvt.u32.u64 %0, t; }"
        : "=r"(a) : "l"(p));
    return a;
}
__device__ __forceinline__ void cp16(uint32_t dst, const void* src) {
    asm volatile("cp.async.ca.shared.global [%0], [%1], 16;" :: "r"(dst), "l"(src));
}
#define CP_COMMIT() asm volatile("cp.async.commit_group;" ::: "memory")
#define CP_WAIT(n)  asm volatile("cp.async.wait_group %0;" :: "n"(n) : "memory")

__device__ __forceinline__ void mma_bf16(float d[4], uint32_t a0, uint32_t a1,
                                         uint32_t a2, uint32_t a3,
                                         uint32_t b0, uint32_t b1) {
    asm volatile(
        "mma.sync.aligned.m16n8k16.row.col.f32.bf16.bf16.f32 "
        "{%0,%1,%2,%3}, {%4,%5,%6,%7}, {%8,%9}, {%0,%1,%2,%3};"
        : "+f"(d[0]), "+f"(d[1]), "+f"(d[2]), "+f"(d[3])
        : "r"(a0), "r"(a1), "r"(a2), "r"(a3), "r"(b0), "r"(b1));
}
__device__ __forceinline__ void ldsm_x4(uint32_t& r0, uint32_t& r1,
                                        uint32_t& r2, uint32_t& r3, uint32_t a) {
    asm volatile("ldmatrix.sync.aligned.m8n8.x4.shared.b16 {%0,%1,%2,%3}, [%4];"
                 : "=r"(r0), "=r"(r1), "=r"(r2), "=r"(r3) : "r"(a));
}
__device__ __forceinline__ float bflo(uint32_t u) { return __uint_as_float(u << 16); }
__device__ __forceinline__ float bfhi(uint32_t u) { return __uint_as_float(u & 0xffff0000u); }

// ---------------- fused weight transpose -> bf16 (all four) ----------------
__global__ void transpose_all_kernel(
    const float* __restrict__ qkv_w, const float* __restrict__ proj_w,
    const float* __restrict__ fc1_w, const float* __restrict__ fc2_w)
{
    int i = blockIdx.x * 256 + threadIdx.x;
    if (i < 196608) {
        int n = i / 256, k = i - n * 256;           // Kd=256, Nd=768
        g_wq[i] = __float2bfloat16(qkv_w[(size_t)k * 768 + n]);
    } else if (i < 262144) {
        int j = i - 196608;
        int n = j / 256, k = j - n * 256;           // 256x256
        g_wp[j] = __float2bfloat16(proj_w[(size_t)k * 256 + n]);
    } else if (i < 524288) {
        int j = i - 262144;
        int n = j / 256, k = j - n * 256;           // Kd=256, Nd=1024
        g_w1[j] = __float2bfloat16(fc1_w[(size_t)k * 1024 + n]);
    } else {
        int j = i - 524288;
        int n = j / 1024, k = j - n * 1024;         // Kd=1024, Nd=256
        g_w2[j] = __float2bfloat16(fc2_w[(size_t)k * 256 + n]);
    }
}

// ---------------- fused CPE + build x + LN1 ----------------
__global__ void __launch_bounds__(256) cpe_ln1_kernel(
    const float* __restrict__ data, const float* __restrict__ relay,
    const int* __restrict__ neigh, const float* __restrict__ cpe_w,
    const float* __restrict__ bn_gamma, const float* __restrict__ bn_beta,
    const float* __restrict__ bn_mean, const float* __restrict__ bn_var,
    const float* __restrict__ g, const float* __restrict__ b)
{
    int warp = threadIdx.x >> 5, lane = threadIdx.x & 31;
    int gr = blockIdx.x * 8 + warp;
    int w = gr / SDIM, s = gr - w * SDIM;

    float2 v[4];
    if (s == 0) {
        const float2* src = (const float2*)(relay + (size_t)w * CDIM);
        #pragma unroll
        for (int i = 0; i < 4; i++) v[i] = src[lane + i * 32];
    } else {
        int n = w * KTOK + s - 1;
        int nb = (lane < KC) ? neigh[(size_t)n * KC + lane] : 0;
        float2 acc[4];
        #pragma unroll
        for (int i = 0; i < 4; i++) acc[i] = make_float2(0.f, 0.f);
        #pragma unroll
        for (int k = 0; k < KC; k++) {
            int idx = __shfl_sync(0xffffffffu, nb, k);
            const float2* drow = (const float2*)(data + (size_t)idx * CDIM);
            const float2* wrow = (const float2*)(cpe_w + k * CDIM);
            #pragma unroll
            for (int i = 0; i < 4; i++) {
                float2 d = drow[lane + i * 32], ww = wrow[lane + i * 32];
                acc[i].x = fmaf(d.x, ww.x, acc[i].x);
                acc[i].y = fmaf(d.y, ww.y, acc[i].y);
            }
        }
        const float2* drow = (const float2*)(data + (size_t)n * CDIM);
        const float2* bm = (const float2*)bn_mean;
        const float2* bv = (const float2*)bn_var;
        const float2* bg = (const float2*)bn_gamma;
        const float2* bb = (const float2*)bn_beta;
        #pragma unroll
        for (int i = 0; i < 4; i++) {
            int c = lane + i * 32;
            float2 d = drow[c], m = bm[c], va = bv[c], ga = bg[c], be = bb[c];
            v[i].x = d.x + (acc[i].x - m.x) * rsqrtf(va.x + EPS) * ga.x + be.x;
            v[i].y = d.y + (acc[i].y - m.y) * rsqrtf(va.y + EPS) * ga.y + be.y;
        }
    }

    float sm = 0.f, s2 = 0.f;
    #pragma unroll
    for (int i = 0; i < 4; i++) {
        sm += v[i].x + v[i].y;
        s2 = fmaf(v[i].x, v[i].x, fmaf(v[i].y, v[i].y, s2));
    }
    #pragma unroll
    for (int o = 16; o; o >>= 1) {
        sm += __shfl_xor_sync(0xffffffffu, sm, o);
        s2 += __shfl_xor_sync(0xffffffffu, s2, o);
    }
    float mu = sm * (1.f / CDIM);
    float rs = rsqrtf(s2 * (1.f / CDIM) - mu * mu + EPS);
    float2* xo = (float2*)(g_x + (size_t)gr * CDIM);
    uint32_t* ho = (uint32_t*)(g_h + (size_t)gr * CDIM);
    const float2* gg = (const float2*)g;
    const float2* gb = (const float2*)b;
    #pragma unroll
    for (int i = 0; i < 4; i++) {
        int c = lane + i * 32;
        xo[c] = v[i];
        float2 ga = gg[c], be = gb[c];
        __nv_bfloat162 h = __floats2bfloat162_rn(
            (v[i].x - mu) * rs * ga.x + be.x,
            (v[i].y - mu) * rs * ga.y + be.y);
        ho[c] = *(uint32_t*)&h;
    }
}

// ---------------- LN2: g_x2 (fp32) -> g_h2 (bf16) ----------------
__global__ void __launch_bounds__(256) ln2_kernel(
    const float* __restrict__ g, const float* __restrict__ b)
{
    int warp = threadIdx.x >> 5, lane = threadIdx.x & 31;
    int gr = blockIdx.x * 8 + warp;
    const float2* src = (const float2*)(g_x2 + (size_t)gr * CDIM);
    float2 v[4];
    float sm = 0.f, s2 = 0.f;
    #pragma unroll
    for (int i = 0; i < 4; i++) {
        v[i] = src[lane + i * 32];
        sm += v[i].x + v[i].y;
        s2 = fmaf(v[i].x, v[i].x, fmaf(v[i].y, v[i].y, s2));
    }
    #pragma unroll
    for (int o = 16; o; o >>= 1) {
        sm += __shfl_xor_sync(0xffffffffu, sm, o);
        s2 += __shfl_xor_sync(0xffffffffu, s2, o);
    }
    float mu = sm * (1.f / CDIM);
    float rs = rsqrtf(s2 * (1.f / CDIM) - mu * mu + EPS);
    uint32_t* ho = (uint32_t*)(g_h2 + (size_t)gr * CDIM);
    const float2* gg = (const float2*)g;
    const float2* gb = (const float2*)b;
    #pragma unroll
    for (int i = 0; i < 4; i++) {
        int c = lane + i * 32;
        float2 ga = gg[c], be = gb[c];
        __nv_bfloat162 h = __floats2bfloat162_rn(
            (v[i].x - mu) * rs * ga.x + be.x,
            (v[i].y - mu) * rs * ga.y + be.y);
        ho[c] = *(uint32_t*)&h;
    }
}

// ---------------- attention v6: single-pass, bf16 K/V, dot ILP ----------------
// block = window, 288 threads (264 active: one per (head, query)).
// smem: K/V bf16 [33 rows][264 uint32] (K words 0..127, V 128..255, pad 8).
// Single sweep, 4 partial dot accumulators to break the RAW chain.
#define KVU 264
#define ATTN_SMEM (SDIM * KVU * 4)                   /* 34848 B */

__global__ void __launch_bounds__(288) attn_kernel()
{
    extern __shared__ uint32_t skv[];                // [33][264] bf16x2 words
    int w = blockIdx.x, tid = threadIdx.x;

    const uint4* src4 = (const uint4*)(g_qkv + (size_t)w * SDIM * 768);
    for (int i = tid; i < SDIM * 64; i += 288) {
        int r = i >> 6, c = i & 63;
        uint4 q4 = src4[r * 96 + 32 + c];
        *(uint4*)(skv + r * KVU + c * 4) = q4;
    }
    __syncthreads();

    if (tid < HEADS * SDIM) {
        int h = tid / SDIM, s = tid - h * SDIM;
        const float scale = 0.17677669529663687f;

        float q[DHEAD];
        {
            const uint32_t* qsrc = (const uint32_t*)(
                g_qkv + ((size_t)w * SDIM + s) * 768) + h * 16;
            #pragma unroll
            for (int i = 0; i < 16; i++) {
                uint32_t p = qsrc[i];
                q[2 * i]     = bflo(p) * scale;
                q[2 * i + 1] = bfhi(p) * scale;
            }
        }

        float o[DHEAD];
        #pragma unroll
        for (int d = 0; d < DHEAD; d++) o[d] = 0.f;
        float ssum = 0.f;

        #pragma unroll 1
        for (int t = 0; t < SDIM; t++) {
            const uint4* kr = (const uint4*)(skv + t * KVU + h * 16);
            float d0 = 0.f, d1 = 0.f, d2 = 0.f, d3 = 0.f;  // 4-way ILP
            #pragma unroll
            for (int j = 0; j < 4; j++) {
                uint4 kk = kr[j];
                d0 = fmaf(q[8 * j],     bflo(kk.x), d0);
                d1 = fmaf(q[8 * j + 1], bfhi(kk.x), d1);
                d2 = fmaf(q[8 * j + 2], bflo(kk.y), d2);
                d3 = fmaf(q[8 * j + 3], bfhi(kk.y), d3);
                d0 = fmaf(q[8 * j + 4], bflo(kk.z), d0);
                d1 = fmaf(q[8 * j + 5], bfhi(kk.z), d1);
                d2 = fmaf(q[8 * j + 6], bflo(kk.w), d2);
                d3 = fmaf(q[8 * j + 7], bfhi(kk.w), d3);
            }
            float e = __expf((d0 + d1) + (d2 + d3));
            ssum += e;
            const uint4* vr = (const uint4*)(skv + t * KVU + 128 + h * 16);
            #pragma unroll
            for (int j = 0; j < 4; j++) {
                uint4 vv = vr[j];
                o[8 * j]     = fmaf(e, bflo(vv.x), o[8 * j]);
                o[8 * j + 1] = fmaf(e, bfhi(vv.x), o[8 * j + 1]);
                o[8 * j + 2] = fmaf(e, bflo(vv.y), o[8 * j + 2]);
                o[8 * j + 3] = fmaf(e, bfhi(vv.y), o[8 * j + 3]);
                o[8 * j + 4] = fmaf(e, bflo(vv.z), o[8 * j + 4]);
                o[8 * j + 5] = fmaf(e, bfhi(vv.z), o[8 * j + 5]);
                o[8 * j + 6] = fmaf(e, bflo(vv.w), o[8 * j + 6]);
                o[8 * j + 7] = fmaf(e, bfhi(vv.w), o[8 * j + 7]);
            }
        }
        float inv = 1.f / ssum;
        __nv_bfloat162* dst = (__nv_bfloat162*)(
            g_attn + ((size_t)w * SDIM + s) * CDIM + h * DHEAD);
        #pragma unroll
        for (int i = 0; i < 16; i++)
            dst[i] = __floats2bfloat162_rn(o[2 * i] * inv, o[2 * i + 1] * inv);
    }
}

// ---------------- bf16 mma.sync GEMM (m16n8k16, ldmatrix operands) ----------------
#define CHUNK_K 64
#define SBF     72
#define SBF_B   (SBF * 2)
#define BUF_ELE (256 * SBF)
#define BUF_BYTES (BUF_ELE * 2)
#define GEMM_SMEM (2 * BUF_BYTES)

template<int KT, int NT, int EPI>
__global__ void __launch_bounds__(256) gemm_mma(
    const __nv_bfloat16* __restrict__ A, const __nv_bfloat16* __restrict__ B,
    const float* __restrict__ bias, const float* __restrict__ res,
    void* __restrict__ outp)
{
    extern __shared__ float smemf[];
    __nv_bfloat16* smem = (__nv_bfloat16*)smemf;
    const int tid = threadIdx.x;
    const int wid = tid >> 5, lane = tid & 31;
    const int g = lane >> 2, t = lane & 3;
    const int warp_m = wid & 1, warp_n = wid >> 1;
    const int n0 = blockIdx.x * 128;
    const int m0 = blockIdx.y * 128;
    const uint32_t sbase = smem_u32(smem);

    const int lm = lane >> 3;
    const int lr = lane & 7;
    const uint32_t a_off0 = (uint32_t)(warp_m * 64 + (lm & 1) * 8 + lr) * SBF_B
                          + (uint32_t)(lm >> 1) * 16;
    const uint32_t b_off0 = (uint32_t)(128 * SBF_B)
                          + (uint32_t)(warp_n * 32 + (lm >> 1) * 8 + lr) * SBF_B
                          + (uint32_t)(lm & 1) * 16;

    float acc[4][4][4];
    #pragma unroll
    for (int i = 0; i < 4; i++)
        #pragma unroll
        for (int j = 0; j < 4; j++)
            #pragma unroll
            for (int r = 0; r < 4; r++) acc[i][j][r] = 0.f;

    constexpr int KCH = KT / CHUNK_K;

    auto load_chunk = [&](int s, int kc) {
        uint32_t base = sbase + (uint32_t)s * BUF_BYTES;
        #pragma unroll
        for (int it = 0; it < 4; it++) {
            int idx = it * 256 + tid;
            int row = idx >> 3, seg = idx & 7;
            cp16(base + (uint32_t)(row * SBF_B + seg * 16),
                 A + (size_t)(m0 + row) * KT + kc * CHUNK_K + seg * 8);
        }
        #pragma unroll
        for (int it = 0; it < 4; it++) {
            int idx = it * 256 + tid;
            int row = idx >> 3, seg = idx & 7;
            cp16(base + (uint32_t)(128 * SBF_B + row * SBF_B + seg * 16),
                 B + (size_t)(n0 + row) * KT + kc * CHUNK_K + seg * 8);
        }
    };

    load_chunk(0, 0); CP_COMMIT();

    for (int kc = 0; kc < KCH; kc++) {
        int s = kc & 1;
        if (kc + 1 < KCH) {
            load_chunk((kc + 1) & 1, kc + 1); CP_COMMIT();
            CP_WAIT(1);
        } else {
            CP_WAIT(0);
        }
        __syncthreads();

        uint32_t abase = sbase + (uint32_t)s * BUF_BYTES + a_off0;
        uint32_t bbase = sbase + (uint32_t)s * BUF_BYTES + b_off0;

        #pragma unroll
        for (int ks = 0; ks < 4; ks++) {
            uint32_t kb = (uint32_t)ks * 32;
            uint32_t bf[4][2];
            ldsm_x4(bf[0][0], bf[0][1], bf[1][0], bf[1][1], bbase + kb);
            ldsm_x4(bf[2][0], bf[2][1], bf[3][0], bf[3][1],
                    bbase + kb + 16u * SBF_B);
            #pragma unroll
            for (int mt = 0; mt < 4; mt++) {
                uint32_t a0, a1, a2, a3;
                ldsm_x4(a0, a1, a2, a3, abase + kb + (uint32_t)mt * 16u * SBF_B);
                #pragma unroll
                for (int nt = 0; nt < 4; nt++)
                    mma_bf16(acc[mt][nt], a0, a1, a2, a3, bf[nt][0], bf[nt][1]);
            }
        }
        __syncthreads();
    }

    float* stg = smemf;
    #pragma unroll
    for (int mt = 0; mt < 4; mt++) {
        #pragma unroll
        for (int nt = 0; nt < 4; nt++) {
            int row = warp_m * 64 + mt * 16 + g;
            int col = warp_n * 32 + nt * 8 + 2 * t;
            stg[row * 132 + col]           = acc[mt][nt][0];
            stg[row * 132 + col + 1]       = acc[mt][nt][1];
            stg[(row + 8) * 132 + col]     = acc[mt][nt][2];
            stg[(row + 8) * 132 + col + 1] = acc[mt][nt][3];
        }
    }
    __syncthreads();

    if (EPI == 0 || EPI == 2) {
        int cp = tid & 63;
        int rb = tid >> 6;
        float b0 = bias[n0 + 2 * cp], b1 = bias[n0 + 2 * cp + 1];
        uint32_t* ob = (uint32_t*)outp;
        #pragma unroll 4
        for (int i = 0; i < 32; i++) {
            int r = rb + i * 4;
            int gr = m0 + r;
            float v0 = stg[r * 132 + 2 * cp] + b0;
            float v1 = stg[r * 132 + 2 * cp + 1] + b1;
            if (EPI == 2) {
                float x3 = v0 * v0 * v0;
                float th = tanhf(0.7978845608028654f * (v0 + 0.044715f * x3));
                v0 = 0.5f * v0 * (1.f + th);
                x3 = v1 * v1 * v1;
                th = tanhf(0.7978845608028654f * (v1 + 0.044715f * x3));
                v1 = 0.5f * v1 * (1.f + th);
            }
            __nv_bfloat162 pk = __floats2bfloat162_rn(v0, v1);
            ob[((size_t)gr * NT + n0) / 2 + cp] = *(uint32_t*)&pk;
        }
    } else {
        int col = tid & 127;
        int r0  = tid >> 7;
        float bi = bias[n0 + col];
        float* of = (float*)outp;
        #pragma unroll 4
        for (int i = 0; i < 64; i++) {
            int r = r0 + i * 2;
            int gr = m0 + r;
            float v = stg[r * 132 + col] + bi + res[(size_t)gr * NT + n0 + col];
            if (EPI == 3) {
                int w = gr / SDIM, sx = gr - (gr / SDIM) * SDIM;
                size_t dst = (sx == 0)
                    ? ((size_t)NTOK * CDIM + (size_t)w * CDIM + n0 + col)
                    : (((size_t)(w * KTOK + sx - 1)) * CDIM + n0 + col);
                of[dst] = v;
            } else {
                of[(size_t)gr * NT + n0 + col] = v;
            }
        }
    }
}

// ---------------------------------------------------------------------------
extern "C" void kernel_launch(void* const* d_in, const int* in_sizes, int n_in,
                              void* d_out, int out_size)
{
    const float* data     = (const float*)d_in[0];
    const float* relay    = (const float*)d_in[1];
    const int*   neigh    = (const int*)  d_in[2];
    const float* cpe_w    = (const float*)d_in[3];
    const float* bn_gamma = (const float*)d_in[4];
    const float* bn_beta  = (const float*)d_in[5];
    const float* bn_mean  = (const float*)d_in[6];
    const float* bn_var   = (const float*)d_in[7];
    const float* norm1_g  = (const float*)d_in[8];
    const float* norm1_b  = (const float*)d_in[9];
    const float* qkv_w    = (const float*)d_in[10];
    const float* qkv_b    = (const float*)d_in[11];
    const float* proj_w   = (const float*)d_in[12];
    const float* proj_b   = (const float*)d_in[13];
    const float* norm2_g  = (const float*)d_in[14];
    const float* norm2_b  = (const float*)d_in[15];
    const float* fc1_w    = (const float*)d_in[16];
    const float* fc1_b    = (const float*)d_in[17];
    const float* fc2_w    = (const float*)d_in[18];
    const float* fc2_b    = (const float*)d_in[19];
    float* out = (float*)d_out;

    static bool inited = false;
    static __nv_bfloat16 *p_h, *p_h2, *p_qkv, *p_attn, *p_f1;
    static __nv_bfloat16 *p_wq, *p_wp, *p_w1, *p_w2;
    static float *p_x, *p_x2;
    if (!inited) {
        cudaFuncSetAttribute(gemm_mma<256, 768, 0>,
            cudaFuncAttributeMaxDynamicSharedMemorySize, GEMM_SMEM);
        cudaFuncSetAttribute(gemm_mma<256, 256, 1>,
            cudaFuncAttributeMaxDynamicSharedMemorySize, GEMM_SMEM);
        cudaFuncSetAttribute(gemm_mma<256, 1024, 2>,
            cudaFuncAttributeMaxDynamicSharedMemorySize, GEMM_SMEM);
        cudaFuncSetAttribute(gemm_mma<1024, 256, 3>,
            cudaFuncAttributeMaxDynamicSharedMemorySize, GEMM_SMEM);
        cudaFuncSetAttribute(attn_kernel,
            cudaFuncAttributeMaxDynamicSharedMemorySize, ATTN_SMEM);
        void* t;
        cudaGetSymbolAddress(&t, g_h);    p_h    = (__nv_bfloat16*)t;
        cudaGetSymbolAddress(&t, g_h2);   p_h2   = (__nv_bfloat16*)t;
        cudaGetSymbolAddress(&t, g_qkv);  p_qkv  = (__nv_bfloat16*)t;
        cudaGetSymbolAddress(&t, g_attn); p_attn = (__nv_bfloat16*)t;
        cudaGetSymbolAddress(&t, g_f1);   p_f1   = (__nv_bfloat16*)t;
        cudaGetSymbolAddress(&t, g_x);    p_x    = (float*)t;
        cudaGetSymbolAddress(&t, g_x2);   p_x2   = (float*)t;
        cudaGetSymbolAddress(&t, g_wq);   p_wq   = (__nv_bfloat16*)t;
        cudaGetSymbolAddress(&t, g_wp);   p_wp   = (__nv_bfloat16*)t;
        cudaGetSymbolAddress(&t, g_w1);   p_w1   = (__nv_bfloat16*)t;
        cudaGetSymbolAddress(&t, g_w2);   p_w2   = (__nv_bfloat16*)t;
        inited = true;
    }

    transpose_all_kernel<<<786432 / 256, 256>>>(qkv_w, proj_w, fc1_w, fc2_w);

    cpe_ln1_kernel<<<RTOT / 8, 256>>>(data, relay, neigh, cpe_w,
                                      bn_gamma, bn_beta, bn_mean, bn_var,
                                      norm1_g, norm1_b);

    const int GB = RTOT / 128;  // 1056
    gemm_mma<256, 768, 0><<<dim3(6, GB), 256, GEMM_SMEM>>>(p_h, p_wq, qkv_b, nullptr, p_qkv);

    attn_kernel<<<W_WIN, 288, ATTN_SMEM>>>();

    gemm_mma<256, 256, 1><<<dim3(2, GB), 256, GEMM_SMEM>>>(p_attn, p_wp, proj_b, p_x, p_x2);

    ln2_kernel<<<RTOT / 8, 256>>>(norm2_g, norm2_b);

    gemm_mma<256, 1024, 2><<<dim3(8, GB), 256, GEMM_SMEM>>>(p_h2, p_w1, fc1_b, nullptr, p_f1);

    gemm_mma<1024, 256, 3><<<dim3(2, GB), 256, GEMM_SMEM>>>(p_f1, p_w2, fc2_b, p_x2, out);
}

// round 14
// speedup vs baseline: 1.1915x; 1.0531x over previous
#include <cuda_runtime.h>
#include <cuda_bf16.h>
#include <math.h>
#include <stdint.h>

#define W_WIN 4096
#define KTOK  32
#define CDIM  256
#define HEADS 8
#define DHEAD 32
#define NTOK  (W_WIN * KTOK)
#define KC    27
#define SDIM  33
#define RTOT  (W_WIN * SDIM)
#define EPS   1e-5f

// ---------------- device scratch ----------------
__device__ float g_x [(size_t)RTOT * CDIM];                 // residual 1 (fp32)
__device__ float g_x2[(size_t)RTOT * CDIM];                 // residual 2 (fp32)
__device__ __nv_bfloat16 g_databf[(size_t)NTOK * CDIM];     // bf16 mirror of data
__device__ __nv_bfloat16 g_h   [(size_t)RTOT * CDIM];       // LN1 out
__device__ __nv_bfloat16 g_h2  [(size_t)RTOT * CDIM];       // LN2 out
__device__ __nv_bfloat16 g_qkv [(size_t)RTOT * 3 * CDIM];   // qkv
__device__ __nv_bfloat16 g_attn[(size_t)RTOT * CDIM];       // attn out
__device__ __nv_bfloat16 g_f1  [(size_t)RTOT * 1024];       // gelu(fc1)
__device__ __nv_bfloat16 g_wq[768 * 256];
__device__ __nv_bfloat16 g_wp[256 * 256];
__device__ __nv_bfloat16 g_w1[1024 * 256];
__device__ __nv_bfloat16 g_w2[256 * 1024];

// ---------------- helpers ----------------
__device__ __forceinline__ uint32_t smem_u32(const void* p) {
    uint32_t a;
    asm("{ .reg .u64 t; cvta.to.shared.u64 t, %1; cvt.u32.u64 %0, t; }"
        : "=r"(a) : "l"(p));
    return a;
}
__device__ __forceinline__ void cp16(uint32_t dst, const void* src) {
    asm volatile("cp.async.ca.shared.global [%0], [%1], 16;" :: "r"(dst), "l"(src));
}
#define CP_COMMIT() asm volatile("cp.async.commit_group;" ::: "memory")
#define CP_WAIT(n)  asm volatile("cp.async.wait_group %0;" :: "n"(n) : "memory")

__device__ __forceinline__ void mma_bf16(float d[4], uint32_t a0, uint32_t a1,
                                         uint32_t a2, uint32_t a3,
                                         uint32_t b0, uint32_t b1) {
    asm volatile(
        "mma.sync.aligned.m16n8k16.row.col.f32.bf16.bf16.f32 "
        "{%0,%1,%2,%3}, {%4,%5,%6,%7}, {%8,%9}, {%0,%1,%2,%3};"
        : "+f"(d[0]), "+f"(d[1]), "+f"(d[2]), "+f"(d[3])
        : "r"(a0), "r"(a1), "r"(a2), "r"(a3), "r"(b0), "r"(b1));
}
__device__ __forceinline__ void ldsm_x4(uint32_t& r0, uint32_t& r1,
                                        uint32_t& r2, uint32_t& r3, uint32_t a) {
    asm volatile("ldmatrix.sync.aligned.m8n8.x4.shared.b16 {%0,%1,%2,%3}, [%4];"
                 : "=r"(r0), "=r"(r1), "=r"(r2), "=r"(r3) : "r"(a));
}
__device__ __forceinline__ float bflo(uint32_t u) { return __uint_as_float(u << 16); }
__device__ __forceinline__ float bfhi(uint32_t u) { return __uint_as_float(u & 0xffff0000u); }

// ---------------- data -> bf16 mirror ----------------
__global__ void __launch_bounds__(256) convert_data_kernel(
    const float* __restrict__ data)
{
    int i = blockIdx.x * 256 + threadIdx.x;   // one uint4 (8 bf16) per thread
    const float4* s = (const float4*)data + (size_t)i * 2;
    float4 a = s[0], b = s[1];
    __nv_bfloat162 p0 = __floats2bfloat162_rn(a.x, a.y);
    __nv_bfloat162 p1 = __floats2bfloat162_rn(a.z, a.w);
    __nv_bfloat162 p2 = __floats2bfloat162_rn(b.x, b.y);
    __nv_bfloat162 p3 = __floats2bfloat162_rn(b.z, b.w);
    uint4 o;
    o.x = *(uint32_t*)&p0; o.y = *(uint32_t*)&p1;
    o.z = *(uint32_t*)&p2; o.w = *(uint32_t*)&p3;
    ((uint4*)g_databf)[i] = o;
}

// ---------------- fused weight transpose -> bf16 (all four) ----------------
__global__ void transpose_all_kernel(
    const float* __restrict__ qkv_w, const float* __restrict__ proj_w,
    const float* __restrict__ fc1_w, const float* __restrict__ fc2_w)
{
    int i = blockIdx.x * 256 + threadIdx.x;
    if (i < 196608) {
        int n = i / 256, k = i - n * 256;
        g_wq[i] = __float2bfloat16(qkv_w[(size_t)k * 768 + n]);
    } else if (i < 262144) {
        int j = i - 196608;
        int n = j / 256, k = j - n * 256;
        g_wp[j] = __float2bfloat16(proj_w[(size_t)k * 256 + n]);
    } else if (i < 524288) {
        int j = i - 262144;
        int n = j / 256, k = j - n * 256;
        g_w1[j] = __float2bfloat16(fc1_w[(size_t)k * 1024 + n]);
    } else {
        int j = i - 524288;
        int n = j / 1024, k = j - n * 1024;
        g_w2[j] = __float2bfloat16(fc2_w[(size_t)k * 256 + n]);
    }
}

// ---------------- fused CPE + build x + LN1 (bf16 gather) ----------------
// warp per row gr; lane owns channels [lane*8, lane*8+8)
__global__ void __launch_bounds__(256) cpe_ln1_kernel(
    const float* __restrict__ data, const float* __restrict__ relay,
    const int* __restrict__ neigh, const float* __restrict__ cpe_w,
    const float* __restrict__ bn_gamma, const float* __restrict__ bn_beta,
    const float* __restrict__ bn_mean, const float* __restrict__ bn_var,
    const float* __restrict__ g, const float* __restrict__ b)
{
    int warp = threadIdx.x >> 5, lane = threadIdx.x & 31;
    int gr = blockIdx.x * 8 + warp;
    int w = gr / SDIM, s = gr - w * SDIM;

    float v[8];
    if (s == 0) {
        const float4* src = (const float4*)(relay + (size_t)w * CDIM) + lane * 2;
        float4 a = src[0], bb4 = src[1];
        v[0] = a.x; v[1] = a.y; v[2] = a.z; v[3] = a.w;
        v[4] = bb4.x; v[5] = bb4.y; v[6] = bb4.z; v[7] = bb4.w;
    } else {
        int n = w * KTOK + s - 1;
        int nb = (lane < KC) ? neigh[(size_t)n * KC + lane] : 0;
        float acc[8];
        #pragma unroll
        for (int i = 0; i < 8; i++) acc[i] = 0.f;
        #pragma unroll
        for (int k = 0; k < KC; k++) {
            int idx = __shfl_sync(0xffffffffu, nb, k);
            uint4 d4 = ((const uint4*)g_databf)[(size_t)idx * 32 + lane];
            const float4* wr = (const float4*)(cpe_w + k * CDIM) + lane * 2;
            float4 w0 = wr[0], w1 = wr[1];
            acc[0] = fmaf(bflo(d4.x), w0.x, acc[0]);
            acc[1] = fmaf(bfhi(d4.x), w0.y, acc[1]);
            acc[2] = fmaf(bflo(d4.y), w0.z, acc[2]);
            acc[3] = fmaf(bfhi(d4.y), w0.w, acc[3]);
            acc[4] = fmaf(bflo(d4.z), w1.x, acc[4]);
            acc[5] = fmaf(bfhi(d4.z), w1.y, acc[5]);
            acc[6] = fmaf(bflo(d4.w), w1.z, acc[6]);
            acc[7] = fmaf(bfhi(d4.w), w1.w, acc[7]);
        }
        const float4* dr = (const float4*)(data + (size_t)n * CDIM) + lane * 2;
        const float4* bm = (const float4*)bn_mean + lane * 2;
        const float4* bv = (const float4*)bn_var + lane * 2;
        const float4* bg = (const float4*)bn_gamma + lane * 2;
        const float4* bb = (const float4*)bn_beta + lane * 2;
        #pragma unroll
        for (int i = 0; i < 2; i++) {
            float4 d = dr[i], m = bm[i], va = bv[i], ga = bg[i], be = bb[i];
            v[4*i]   = d.x + (acc[4*i]   - m.x) * rsqrtf(va.x + EPS) * ga.x + be.x;
            v[4*i+1] = d.y + (acc[4*i+1] - m.y) * rsqrtf(va.y + EPS) * ga.y + be.y;
            v[4*i+2] = d.z + (acc[4*i+2] - m.z) * rsqrtf(va.z + EPS) * ga.z + be.z;
            v[4*i+3] = d.w + (acc[4*i+3] - m.w) * rsqrtf(va.w + EPS) * ga.w + be.w;
        }
    }

    float sm = 0.f, s2 = 0.f;
    #pragma unroll
    for (int i = 0; i < 8; i++) { sm += v[i]; s2 = fmaf(v[i], v[i], s2); }
    #pragma unroll
    for (int o = 16; o; o >>= 1) {
        sm += __shfl_xor_sync(0xffffffffu, sm, o);
        s2 += __shfl_xor_sync(0xffffffffu, s2, o);
    }
    float mu = sm * (1.f / CDIM);
    float rs = rsqrtf(s2 * (1.f / CDIM) - mu * mu + EPS);

    float4* xo = (float4*)(g_x + (size_t)gr * CDIM) + lane * 2;
    xo[0] = make_float4(v[0], v[1], v[2], v[3]);
    xo[1] = make_float4(v[4], v[5], v[6], v[7]);

    const float4* gg = (const float4*)g + lane * 2;
    const float4* gb = (const float4*)b + lane * 2;
    float hh[8];
    #pragma unroll
    for (int i = 0; i < 2; i++) {
        float4 ga = gg[i], be = gb[i];
        hh[4*i]   = (v[4*i]   - mu) * rs * ga.x + be.x;
        hh[4*i+1] = (v[4*i+1] - mu) * rs * ga.y + be.y;
        hh[4*i+2] = (v[4*i+2] - mu) * rs * ga.z + be.z;
        hh[4*i+3] = (v[4*i+3] - mu) * rs * ga.w + be.w;
    }
    __nv_bfloat162 p0 = __floats2bfloat162_rn(hh[0], hh[1]);
    __nv_bfloat162 p1 = __floats2bfloat162_rn(hh[2], hh[3]);
    __nv_bfloat162 p2 = __floats2bfloat162_rn(hh[4], hh[5]);
    __nv_bfloat162 p3 = __floats2bfloat162_rn(hh[6], hh[7]);
    uint4 ho;
    ho.x = *(uint32_t*)&p0; ho.y = *(uint32_t*)&p1;
    ho.z = *(uint32_t*)&p2; ho.w = *(uint32_t*)&p3;
    ((uint4*)(g_h + (size_t)gr * CDIM))[lane] = ho;
}

// ---------------- LN2: g_x2 (fp32) -> g_h2 (bf16) ----------------
__global__ void __launch_bounds__(256) ln2_kernel(
    const float* __restrict__ g, const float* __restrict__ b)
{
    int warp = threadIdx.x >> 5, lane = threadIdx.x & 31;
    int gr = blockIdx.x * 8 + warp;
    const float2* src = (const float2*)(g_x2 + (size_t)gr * CDIM);
    float2 v[4];
    float sm = 0.f, s2 = 0.f;
    #pragma unroll
    for (int i = 0; i < 4; i++) {
        v[i] = src[lane + i * 32];
        sm += v[i].x + v[i].y;
        s2 = fmaf(v[i].x, v[i].x, fmaf(v[i].y, v[i].y, s2));
    }
    #pragma unroll
    for (int o = 16; o; o >>= 1) {
        sm += __shfl_xor_sync(0xffffffffu, sm, o);
        s2 += __shfl_xor_sync(0xffffffffu, s2, o);
    }
    float mu = sm * (1.f / CDIM);
    float rs = rsqrtf(s2 * (1.f / CDIM) - mu * mu + EPS);
    uint32_t* ho = (uint32_t*)(g_h2 + (size_t)gr * CDIM);
    const float2* gg = (const float2*)g;
    const float2* gb = (const float2*)b;
    #pragma unroll
    for (int i = 0; i < 4; i++) {
        int c = lane + i * 32;
        float2 ga = gg[c], be = gb[c];
        __nv_bfloat162 h = __floats2bfloat162_rn(
            (v[i].x - mu) * rs * ga.x + be.x,
            (v[i].y - mu) * rs * ga.y + be.y);
        ho[c] = *(uint32_t*)&h;
    }
}

// ---------------- attention v6: single-pass, bf16 K/V, dot ILP ----------------
#define KVU 264
#define ATTN_SMEM (SDIM * KVU * 4)                   /* 34848 B */

__global__ void __launch_bounds__(288) attn_kernel()
{
    extern __shared__ uint32_t skv[];                // [33][264] bf16x2 words
    int w = blockIdx.x, tid = threadIdx.x;

    const uint4* src4 = (const uint4*)(g_qkv + (size_t)w * SDIM * 768);
    for (int i = tid; i < SDIM * 64; i += 288) {
        int r = i >> 6, c = i & 63;
        uint4 q4 = src4[r * 96 + 32 + c];
        *(uint4*)(skv + r * KVU + c * 4) = q4;
    }
    __syncthreads();

    if (tid < HEADS * SDIM) {
        int h = tid / SDIM, s = tid - h * SDIM;
        const float scale = 0.17677669529663687f;

        float q[DHEAD];
        {
            const uint32_t* qsrc = (const uint32_t*)(
                g_qkv + ((size_t)w * SDIM + s) * 768) + h * 16;
            #pragma unroll
            for (int i = 0; i < 16; i++) {
                uint32_t p = qsrc[i];
                q[2 * i]     = bflo(p) * scale;
                q[2 * i + 1] = bfhi(p) * scale;
            }
        }

        float o[DHEAD];
        #pragma unroll
        for (int d = 0; d < DHEAD; d++) o[d] = 0.f;
        float ssum = 0.f;

        #pragma unroll 1
        for (int t = 0; t < SDIM; t++) {
            const uint4* kr = (const uint4*)(skv + t * KVU + h * 16);
            float d0 = 0.f, d1 = 0.f, d2 = 0.f, d3 = 0.f;
            #pragma unroll
            for (int j = 0; j < 4; j++) {
                uint4 kk = kr[j];
                d0 = fmaf(q[8 * j],     bflo(kk.x), d0);
                d1 = fmaf(q[8 * j + 1], bfhi(kk.x), d1);
                d2 = fmaf(q[8 * j + 2], bflo(kk.y), d2);
                d3 = fmaf(q[8 * j + 3], bfhi(kk.y), d3);
                d0 = fmaf(q[8 * j + 4], bflo(kk.z), d0);
                d1 = fmaf(q[8 * j + 5], bfhi(kk.z), d1);
                d2 = fmaf(q[8 * j + 6], bflo(kk.w), d2);
                d3 = fmaf(q[8 * j + 7], bfhi(kk.w), d3);
            }
            float e = __expf((d0 + d1) + (d2 + d3));
            ssum += e;
            const uint4* vr = (const uint4*)(skv + t * KVU + 128 + h * 16);
            #pragma unroll
            for (int j = 0; j < 4; j++) {
                uint4 vv = vr[j];
                o[8 * j]     = fmaf(e, bflo(vv.x), o[8 * j]);
                o[8 * j + 1] = fmaf(e, bfhi(vv.x), o[8 * j + 1]);
                o[8 * j + 2] = fmaf(e, bflo(vv.y), o[8 * j + 2]);
                o[8 * j + 3] = fmaf(e, bfhi(vv.y), o[8 * j + 3]);
                o[8 * j + 4] = fmaf(e, bflo(vv.z), o[8 * j + 4]);
                o[8 * j + 5] = fmaf(e, bfhi(vv.z), o[8 * j + 5]);
                o[8 * j + 6] = fmaf(e, bflo(vv.w), o[8 * j + 6]);
                o[8 * j + 7] = fmaf(e, bfhi(vv.w), o[8 * j + 7]);
            }
        }
        float inv = 1.f / ssum;
        __nv_bfloat162* dst = (__nv_bfloat162*)(
            g_attn + ((size_t)w * SDIM + s) * CDIM + h * DHEAD);
        #pragma unroll
        for (int i = 0; i < 16; i++)
            dst[i] = __floats2bfloat162_rn(o[2 * i] * inv, o[2 * i + 1] * inv);
    }
}

// ---------------- bf16 mma.sync GEMM (m16n8k16, ldmatrix operands) ----------------
#define CHUNK_K 64
#define SBF     72
#define SBF_B   (SBF * 2)
#define BUF_ELE (256 * SBF)
#define BUF_BYTES (BUF_ELE * 2)
#define GEMM_SMEM (2 * BUF_BYTES)

template<int KT, int NT, int EPI>
__global__ void __launch_bounds__(256) gemm_mma(
    const __nv_bfloat16* __restrict__ A, const __nv_bfloat16* __restrict__ B,
    const float* __restrict__ bias, const float* __restrict__ res,
    void* __restrict__ outp)
{
    extern __shared__ float smemf[];
    __nv_bfloat16* smem = (__nv_bfloat16*)smemf;
    const int tid = threadIdx.x;
    const int wid = tid >> 5, lane = tid & 31;
    const int g = lane >> 2, t = lane & 3;
    const int warp_m = wid & 1, warp_n = wid >> 1;
    const int n0 = blockIdx.x * 128;
    const int m0 = blockIdx.y * 128;
    const uint32_t sbase = smem_u32(smem);

    const int lm = lane >> 3;
    const int lr = lane & 7;
    const uint32_t a_off0 = (uint32_t)(warp_m * 64 + (lm & 1) * 8 + lr) * SBF_B
                          + (uint32_t)(lm >> 1) * 16;
    const uint32_t b_off0 = (uint32_t)(128 * SBF_B)
                          + (uint32_t)(warp_n * 32 + (lm >> 1) * 8 + lr) * SBF_B
                          + (uint32_t)(lm & 1) * 16;

    float acc[4][4][4];
    #pragma unroll
    for (int i = 0; i < 4; i++)
        #pragma unroll
        for (int j = 0; j < 4; j++)
            #pragma unroll
            for (int r = 0; r < 4; r++) acc[i][j][r] = 0.f;

    constexpr int KCH = KT / CHUNK_K;

    auto load_chunk = [&](int s, int kc) {
        uint32_t base = sbase + (uint32_t)s * BUF_BYTES;
        #pragma unroll
        for (int it = 0; it < 4; it++) {
            int idx = it * 256 + tid;
            int row = idx >> 3, seg = idx & 7;
            cp16(base + (uint32_t)(row * SBF_B + seg * 16),
                 A + (size_t)(m0 + row) * KT + kc * CHUNK_K + seg * 8);
        }
        #pragma unroll
        for (int it = 0; it < 4; it++) {
            int idx = it * 256 + tid;
            int row = idx >> 3, seg = idx & 7;
            cp16(base + (uint32_t)(128 * SBF_B + row * SBF_B + seg * 16),
                 B + (size_t)(n0 + row) * KT + kc * CHUNK_K + seg * 8);
        }
    };

    load_chunk(0, 0); CP_COMMIT();

    for (int kc = 0; kc < KCH; kc++) {
        int s = kc & 1;
        if (kc + 1 < KCH) {
            load_chunk((kc + 1) & 1, kc + 1); CP_COMMIT();
            CP_WAIT(1);
        } else {
            CP_WAIT(0);
        }
        __syncthreads();

        uint32_t abase = sbase + (uint32_t)s * BUF_BYTES + a_off0;
        uint32_t bbase = sbase + (uint32_t)s * BUF_BYTES + b_off0;

        #pragma unroll
        for (int ks = 0; ks < 4; ks++) {
            uint32_t kb = (uint32_t)ks * 32;
            uint32_t bf[4][2];
            ldsm_x4(bf[0][0], bf[0][1], bf[1][0], bf[1][1], bbase + kb);
            ldsm_x4(bf[2][0], bf[2][1], bf[3][0], bf[3][1],
                    bbase + kb + 16u * SBF_B);
            #pragma unroll
            for (int mt = 0; mt < 4; mt++) {
                uint32_t a0, a1, a2, a3;
                ldsm_x4(a0, a1, a2, a3, abase + kb + (uint32_t)mt * 16u * SBF_B);
                #pragma unroll
                for (int nt = 0; nt < 4; nt++)
                    mma_bf16(acc[mt][nt], a0, a1, a2, a3, bf[nt][0], bf[nt][1]);
            }
        }
        __syncthreads();
    }

    float* stg = smemf;
    #pragma unroll
    for (int mt = 0; mt < 4; mt++) {
        #pragma unroll
        for (int nt = 0; nt < 4; nt++) {
            int row = warp_m * 64 + mt * 16 + g;
            int col = warp_n * 32 + nt * 8 + 2 * t;
            stg[row * 132 + col]           = acc[mt][nt][0];
            stg[row * 132 + col + 1]       = acc[mt][nt][1];
            stg[(row + 8) * 132 + col]     = acc[mt][nt][2];
            stg[(row + 8) * 132 + col + 1] = acc[mt][nt][3];
        }
    }
    __syncthreads();

    if (EPI == 0 || EPI == 2) {
        int cp = tid & 63;
        int rb = tid >> 6;
        float b0 = bias[n0 + 2 * cp], b1 = bias[n0 + 2 * cp + 1];
        uint32_t* ob = (uint32_t*)outp;
        #pragma unroll 4
        for (int i = 0; i < 32; i++) {
            int r = rb + i * 4;
            int gr = m0 + r;
            float v0 = stg[r * 132 + 2 * cp] + b0;
            float v1 = stg[r * 132 + 2 * cp + 1] + b1;
            if (EPI == 2) {
                float x3 = v0 * v0 * v0;
                float th = tanhf(0.7978845608028654f * (v0 + 0.044715f * x3));
                v0 = 0.5f * v0 * (1.f + th);
                x3 = v1 * v1 * v1;
                th = tanhf(0.7978845608028654f * (v1 + 0.044715f * x3));
                v1 = 0.5f * v1 * (1.f + th);
            }
            __nv_bfloat162 pk = __floats2bfloat162_rn(v0, v1);
            ob[((size_t)gr * NT + n0) / 2 + cp] = *(uint32_t*)&pk;
        }
    } else {
        int col = tid & 127;
        int r0  = tid >> 7;
        float bi = bias[n0 + col];
        float* of = (float*)outp;
        #pragma unroll 4
        for (int i = 0; i < 64; i++) {
            int r = r0 + i * 2;
            int gr = m0 + r;
            float v = stg[r * 132 + col] + bi + res[(size_t)gr * NT + n0 + col];
            if (EPI == 3) {
                int w = gr / SDIM, sx = gr - (gr / SDIM) * SDIM;
                size_t dst = (sx == 0)
                    ? ((size_t)NTOK * CDIM + (size_t)w * CDIM + n0 + col)
                    : (((size_t)(w * KTOK + sx - 1)) * CDIM + n0 + col);
                of[dst] = v;
            } else {
                of[(size_t)gr * NT + n0 + col] = v;
            }
        }
    }
}

// ---------------------------------------------------------------------------
extern "C" void kernel_launch(void* const* d_in, const int* in_sizes, int n_in,
                              void* d_out, int out_size)
{
    const float* data     = (const float*)d_in[0];
    const float* relay    = (const float*)d_in[1];
    const int*   neigh    = (const int*)  d_in[2];
    const float* cpe_w    = (const float*)d_in[3];
    const float* bn_gamma = (const float*)d_in[4];
    const float* bn_beta  = (const float*)d_in[5];
    const float* bn_mean  = (const float*)d_in[6];
    const float* bn_var   = (const float*)d_in[7];
    const float* norm1_g  = (const float*)d_in[8];
    const float* norm1_b  = (const float*)d_in[9];
    const float* qkv_w    = (const float*)d_in[10];
    const float* qkv_b    = (const float*)d_in[11];
    const float* proj_w   = (const float*)d_in[12];
    const float* proj_b   = (const float*)d_in[13];
    const float* norm2_g  = (const float*)d_in[14];
    const float* norm2_b  = (const float*)d_in[15];
    const float* fc1_w    = (const float*)d_in[16];
    const float* fc1_b    = (const float*)d_in[17];
    const float* fc2_w    = (const float*)d_in[18];
    const float* fc2_b    = (const float*)d_in[19];
    float* out = (float*)d_out;

    static bool inited = false;
    static __nv_bfloat16 *p_h, *p_h2, *p_qkv, *p_attn, *p_f1;
    static __nv_bfloat16 *p_wq, *p_wp, *p_w1, *p_w2;
    static float *p_x, *p_x2;
    if (!inited) {
        cudaFuncSetAttribute(gemm_mma<256, 768, 0>,
            cudaFuncAttributeMaxDynamicSharedMemorySize, GEMM_SMEM);
        cudaFuncSetAttribute(gemm_mma<256, 256, 1>,
            cudaFuncAttributeMaxDynamicSharedMemorySize, GEMM_SMEM);
        cudaFuncSetAttribute(gemm_mma<256, 1024, 2>,
            cudaFuncAttributeMaxDynamicSharedMemorySize, GEMM_SMEM);
        cudaFuncSetAttribute(gemm_mma<1024, 256, 3>,
            cudaFuncAttributeMaxDynamicSharedMemorySize, GEMM_SMEM);
        cudaFuncSetAttribute(attn_kernel,
            cudaFuncAttributeMaxDynamicSharedMemorySize, ATTN_SMEM);
        void* t;
        cudaGetSymbolAddress(&t, g_h);    p_h    = (__nv_bfloat16*)t;
        cudaGetSymbolAddress(&t, g_h2);   p_h2   = (__nv_bfloat16*)t;
        cudaGetSymbolAddress(&t, g_qkv);  p_qkv  = (__nv_bfloat16*)t;
        cudaGetSymbolAddress(&t, g_attn); p_attn = (__nv_bfloat16*)t;
        cudaGetSymbolAddress(&t, g_f1);   p_f1   = (__nv_bfloat16*)t;
        cudaGetSymbolAddress(&t, g_x);    p_x    = (float*)t;
        cudaGetSymbolAddress(&t, g_x2);   p_x2   = (float*)t;
        cudaGetSymbolAddress(&t, g_wq);   p_wq   = (__nv_bfloat16*)t;
        cudaGetSymbolAddress(&t, g_wp);   p_wp   = (__nv_bfloat16*)t;
        cudaGetSymbolAddress(&t, g_w1);   p_w1   = (__nv_bfloat16*)t;
        cudaGetSymbolAddress(&t, g_w2);   p_w2   = (__nv_bfloat16*)t;
        inited = true;
    }

    convert_data_kernel<<<NTOK * CDIM / 8 / 256, 256>>>(data);
    transpose_all_kernel<<<786432 / 256, 256>>>(qkv_w, proj_w, fc1_w, fc2_w);

    cpe_ln1_kernel<<<RTOT / 8, 256>>>(data, relay, neigh, cpe_w,
                                      bn_gamma, bn_beta, bn_mean, bn_var,
                                      norm1_g, norm1_b);

    const int GB = RTOT / 128;  // 1056
    gemm_mma<256, 768, 0><<<dim3(6, GB), 256, GEMM_SMEM>>>(p_h, p_wq, qkv_b, nullptr, p_qkv);

    attn_kernel<<<W_WIN, 288, ATTN_SMEM>>>();

    gemm_mma<256, 256, 1><<<dim3(2, GB), 256, GEMM_SMEM>>>(p_attn, p_wp, proj_b, p_x, p_x2);

    ln2_kernel<<<RTOT / 8, 256>>>(norm2_g, norm2_b);

    gemm_mma<256, 1024, 2><<<dim3(8, GB), 256, GEMM_SMEM>>>(p_h2, p_w1, fc1_b, nullptr, p_f1);

    gemm_mma<1024, 256, 3><<<dim3(2, GB), 256, GEMM_SMEM>>>(p_f1, p_w2, fc2_b, p_x2, out);
}

// round 15
// speedup vs baseline: 1.2376x; 1.0387x over previous
#include <cuda_runtime.h>
#include <cuda_bf16.h>
#include <math.h>
#include <stdint.h>

#define W_WIN 4096
#define KTOK  32
#define CDIM  256
#define HEADS 8
#define DHEAD 32
#define NTOK  (W_WIN * KTOK)
#define KC    27
#define SDIM  33
#define RTOT  (W_WIN * SDIM)
#define EPS   1e-5f

// ---------------- device scratch ----------------
__device__ float g_x [(size_t)RTOT * CDIM];
__device__ float g_x2[(size_t)RTOT * CDIM];
__device__ __nv_bfloat16 g_databf[(size_t)NTOK * CDIM];
__device__ __nv_bfloat16 g_h   [(size_t)RTOT * CDIM];
__device__ __nv_bfloat16 g_h2  [(size_t)RTOT * CDIM];
__device__ __nv_bfloat16 g_qkv [(size_t)RTOT * 3 * CDIM];
__device__ __nv_bfloat16 g_attn[(size_t)RTOT * CDIM];
__device__ __nv_bfloat16 g_f1  [(size_t)RTOT * 1024];
__device__ __nv_bfloat16 g_wq[768 * 256];
__device__ __nv_bfloat16 g_wp[256 * 256];
__device__ __nv_bfloat16 g_w1[1024 * 256];
__device__ __nv_bfloat16 g_w2[256 * 1024];

// ---------------- helpers ----------------
__device__ __forceinline__ uint32_t smem_u32(const void* p) {
    uint32_t a;
    asm("{ .reg .u64 t; cvta.to.shared.u64 t, %1; cvt.u32.u64 %0, t; }"
        : "=r"(a) : "l"(p));
    return a;
}
__device__ __forceinline__ void cp16(uint32_t dst, const void* src) {
    asm volatile("cp.async.ca.shared.global [%0], [%1], 16;" :: "r"(dst), "l"(src));
}
#define CP_COMMIT() asm volatile("cp.async.commit_group;" ::: "memory")
#define CP_WAIT(n)  asm volatile("cp.async.wait_group %0;" :: "n"(n) : "memory")

__device__ __forceinline__ void mma_bf16(float d[4], uint32_t a0, uint32_t a1,
                                         uint32_t a2, uint32_t a3,
                                         uint32_t b0, uint32_t b1) {
    asm volatile(
        "mma.sync.aligned.m16n8k16.row.col.f32.bf16.bf16.f32 "
        "{%0,%1,%2,%3}, {%4,%5,%6,%7}, {%8,%9}, {%0,%1,%2,%3};"
        : "+f"(d[0]), "+f"(d[1]), "+f"(d[2]), "+f"(d[3])
        : "r"(a0), "r"(a1), "r"(a2), "r"(a3), "r"(b0), "r"(b1));
}
__device__ __forceinline__ void ldsm_x4(uint32_t& r0, uint32_t& r1,
                                        uint32_t& r2, uint32_t& r3, uint32_t a) {
    asm volatile("ldmatrix.sync.aligned.m8n8.x4.shared.b16 {%0,%1,%2,%3}, [%4];"
                 : "=r"(r0), "=r"(r1), "=r"(r2), "=r"(r3) : "r"(a));
}
__device__ __forceinline__ float bflo(uint32_t u) { return __uint_as_float(u << 16); }
__device__ __forceinline__ float bfhi(uint32_t u) { return __uint_as_float(u & 0xffff0000u); }

__device__ __forceinline__ float gelu_fast(float v) {
    float x3 = v * v * v;
    float u = 0.7978845608028654f * (v + 0.044715f * x3);
    float th;
    asm("tanh.approx.f32 %0, %1;" : "=f"(th) : "f"(u));
    return 0.5f * v * (1.f + th);
}

// ---------------- data -> bf16 mirror ----------------
__global__ void __launch_bounds__(256) convert_data_kernel(
    const float* __restrict__ data)
{
    int i = blockIdx.x * 256 + threadIdx.x;
    const float4* s = (const float4*)data + (size_t)i * 2;
    float4 a = s[0], b = s[1];
    __nv_bfloat162 p0 = __floats2bfloat162_rn(a.x, a.y);
    __nv_bfloat162 p1 = __floats2bfloat162_rn(a.z, a.w);
    __nv_bfloat162 p2 = __floats2bfloat162_rn(b.x, b.y);
    __nv_bfloat162 p3 = __floats2bfloat162_rn(b.z, b.w);
    uint4 o;
    o.x = *(uint32_t*)&p0; o.y = *(uint32_t*)&p1;
    o.z = *(uint32_t*)&p2; o.w = *(uint32_t*)&p3;
    ((uint4*)g_databf)[i] = o;
}

// ---------------- fused weight transpose -> bf16 (all four) ----------------
__global__ void transpose_all_kernel(
    const float* __restrict__ qkv_w, const float* __restrict__ proj_w,
    const float* __restrict__ fc1_w, const float* __restrict__ fc2_w)
{
    int i = blockIdx.x * 256 + threadIdx.x;
    if (i < 196608) {
        int n = i / 256, k = i - n * 256;
        g_wq[i] = __float2bfloat16(qkv_w[(size_t)k * 768 + n]);
    } else if (i < 262144) {
        int j = i - 196608;
        int n = j / 256, k = j - n * 256;
        g_wp[j] = __float2bfloat16(proj_w[(size_t)k * 256 + n]);
    } else if (i < 524288) {
        int j = i - 262144;
        int n = j / 256, k = j - n * 256;
        g_w1[j] = __float2bfloat16(fc1_w[(size_t)k * 1024 + n]);
    } else {
        int j = i - 524288;
        int n = j / 1024, k = j - n * 1024;
        g_w2[j] = __float2bfloat16(fc2_w[(size_t)k * 256 + n]);
    }
}

// ---------------- fused CPE + build x + LN1 (bf16 gather) ----------------
__global__ void __launch_bounds__(256) cpe_ln1_kernel(
    const float* __restrict__ data, const float* __restrict__ relay,
    const int* __restrict__ neigh, const float* __restrict__ cpe_w,
    const float* __restrict__ bn_gamma, const float* __restrict__ bn_beta,
    const float* __restrict__ bn_mean, const float* __restrict__ bn_var,
    const float* __restrict__ g, const float* __restrict__ b)
{
    int warp = threadIdx.x >> 5, lane = threadIdx.x & 31;
    int gr = blockIdx.x * 8 + warp;
    int w = gr / SDIM, s = gr - w * SDIM;

    float v[8];
    if (s == 0) {
        const float4* src = (const float4*)(relay + (size_t)w * CDIM) + lane * 2;
        float4 a = src[0], bb4 = src[1];
        v[0] = a.x; v[1] = a.y; v[2] = a.z; v[3] = a.w;
        v[4] = bb4.x; v[5] = bb4.y; v[6] = bb4.z; v[7] = bb4.w;
    } else {
        int n = w * KTOK + s - 1;
        int nb = (lane < KC) ? neigh[(size_t)n * KC + lane] : 0;
        float acc[8];
        #pragma unroll
        for (int i = 0; i < 8; i++) acc[i] = 0.f;
        #pragma unroll
        for (int k = 0; k < KC; k++) {
            int idx = __shfl_sync(0xffffffffu, nb, k);
            uint4 d4 = ((const uint4*)g_databf)[(size_t)idx * 32 + lane];
            const float4* wr = (const float4*)(cpe_w + k * CDIM) + lane * 2;
            float4 w0 = wr[0], w1 = wr[1];
            acc[0] = fmaf(bflo(d4.x), w0.x, acc[0]);
            acc[1] = fmaf(bfhi(d4.x), w0.y, acc[1]);
            acc[2] = fmaf(bflo(d4.y), w0.z, acc[2]);
            acc[3] = fmaf(bfhi(d4.y), w0.w, acc[3]);
            acc[4] = fmaf(bflo(d4.z), w1.x, acc[4]);
            acc[5] = fmaf(bfhi(d4.z), w1.y, acc[5]);
            acc[6] = fmaf(bflo(d4.w), w1.z, acc[6]);
            acc[7] = fmaf(bfhi(d4.w), w1.w, acc[7]);
        }
        const float4* dr = (const float4*)(data + (size_t)n * CDIM) + lane * 2;
        const float4* bm = (const float4*)bn_mean + lane * 2;
        const float4* bv = (const float4*)bn_var + lane * 2;
        const float4* bg = (const float4*)bn_gamma + lane * 2;
        const float4* bb = (const float4*)bn_beta + lane * 2;
        #pragma unroll
        for (int i = 0; i < 2; i++) {
            float4 d = dr[i], m = bm[i], va = bv[i], ga = bg[i], be = bb[i];
            v[4*i]   = d.x + (acc[4*i]   - m.x) * rsqrtf(va.x + EPS) * ga.x + be.x;
            v[4*i+1] = d.y + (acc[4*i+1] - m.y) * rsqrtf(va.y + EPS) * ga.y + be.y;
            v[4*i+2] = d.z + (acc[4*i+2] - m.z) * rsqrtf(va.z + EPS) * ga.z + be.z;
            v[4*i+3] = d.w + (acc[4*i+3] - m.w) * rsqrtf(va.w + EPS) * ga.w + be.w;
        }
    }

    float sm = 0.f, s2 = 0.f;
    #pragma unroll
    for (int i = 0; i < 8; i++) { sm += v[i]; s2 = fmaf(v[i], v[i], s2); }
    #pragma unroll
    for (int o = 16; o; o >>= 1) {
        sm += __shfl_xor_sync(0xffffffffu, sm, o);
        s2 += __shfl_xor_sync(0xffffffffu, s2, o);
    }
    float mu = sm * (1.f / CDIM);
    float rs = rsqrtf(s2 * (1.f / CDIM) - mu * mu + EPS);

    float4* xo = (float4*)(g_x + (size_t)gr * CDIM) + lane * 2;
    xo[0] = make_float4(v[0], v[1], v[2], v[3]);
    xo[1] = make_float4(v[4], v[5], v[6], v[7]);

    const float4* gg = (const float4*)g + lane * 2;
    const float4* gb = (const float4*)b + lane * 2;
    float hh[8];
    #pragma unroll
    for (int i = 0; i < 2; i++) {
        float4 ga = gg[i], be = gb[i];
        hh[4*i]   = (v[4*i]   - mu) * rs * ga.x + be.x;
        hh[4*i+1] = (v[4*i+1] - mu) * rs * ga.y + be.y;
        hh[4*i+2] = (v[4*i+2] - mu) * rs * ga.z + be.z;
        hh[4*i+3] = (v[4*i+3] - mu) * rs * ga.w + be.w;
    }
    __nv_bfloat162 p0 = __floats2bfloat162_rn(hh[0], hh[1]);
    __nv_bfloat162 p1 = __floats2bfloat162_rn(hh[2], hh[3]);
    __nv_bfloat162 p2 = __floats2bfloat162_rn(hh[4], hh[5]);
    __nv_bfloat162 p3 = __floats2bfloat162_rn(hh[6], hh[7]);
    uint4 ho;
    ho.x = *(uint32_t*)&p0; ho.y = *(uint32_t*)&p1;
    ho.z = *(uint32_t*)&p2; ho.w = *(uint32_t*)&p3;
    ((uint4*)(g_h + (size_t)gr * CDIM))[lane] = ho;
}

// ---------------- LN2: g_x2 (fp32) -> g_h2 (bf16) ----------------
__global__ void __launch_bounds__(256) ln2_kernel(
    const float* __restrict__ g, const float* __restrict__ b)
{
    int warp = threadIdx.x >> 5, lane = threadIdx.x & 31;
    int gr = blockIdx.x * 8 + warp;
    const float2* src = (const float2*)(g_x2 + (size_t)gr * CDIM);
    float2 v[4];
    float sm = 0.f, s2 = 0.f;
    #pragma unroll
    for (int i = 0; i < 4; i++) {
        v[i] = src[lane + i * 32];
        sm += v[i].x + v[i].y;
        s2 = fmaf(v[i].x, v[i].x, fmaf(v[i].y, v[i].y, s2));
    }
    #pragma unroll
    for (int o = 16; o; o >>= 1) {
        sm += __shfl_xor_sync(0xffffffffu, sm, o);
        s2 += __shfl_xor_sync(0xffffffffu, s2, o);
    }
    float mu = sm * (1.f / CDIM);
    float rs = rsqrtf(s2 * (1.f / CDIM) - mu * mu + EPS);
    uint32_t* ho = (uint32_t*)(g_h2 + (size_t)gr * CDIM);
    const float2* gg = (const float2*)g;
    const float2* gb = (const float2*)b;
    #pragma unroll
    for (int i = 0; i < 4; i++) {
        int c = lane + i * 32;
        float2 ga = gg[c], be = gb[c];
        __nv_bfloat162 h = __floats2bfloat162_rn(
            (v[i].x - mu) * rs * ga.x + be.x,
            (v[i].y - mu) * rs * ga.y + be.y);
        ho[c] = *(uint32_t*)&h;
    }
}

// ---------------- attention v6: single-pass, bf16 K/V, dot ILP ----------------
#define KVU 264
#define ATTN_SMEM (SDIM * KVU * 4)

__global__ void __launch_bounds__(288) attn_kernel()
{
    extern __shared__ uint32_t skv[];
    int w = blockIdx.x, tid = threadIdx.x;

    const uint4* src4 = (const uint4*)(g_qkv + (size_t)w * SDIM * 768);
    for (int i = tid; i < SDIM * 64; i += 288) {
        int r = i >> 6, c = i & 63;
        uint4 q4 = src4[r * 96 + 32 + c];
        *(uint4*)(skv + r * KVU + c * 4) = q4;
    }
    __syncthreads();

    if (tid < HEADS * SDIM) {
        int h = tid / SDIM, s = tid - h * SDIM;
        const float scale = 0.17677669529663687f;

        float q[DHEAD];
        {
            const uint32_t* qsrc = (const uint32_t*)(
                g_qkv + ((size_t)w * SDIM + s) * 768) + h * 16;
            #pragma unroll
            for (int i = 0; i < 16; i++) {
                uint32_t p = qsrc[i];
                q[2 * i]     = bflo(p) * scale;
                q[2 * i + 1] = bfhi(p) * scale;
            }
        }

        float o[DHEAD];
        #pragma unroll
        for (int d = 0; d < DHEAD; d++) o[d] = 0.f;
        float ssum = 0.f;

        #pragma unroll 1
        for (int t = 0; t < SDIM; t++) {
            const uint4* kr = (const uint4*)(skv + t * KVU + h * 16);
            float d0 = 0.f, d1 = 0.f, d2 = 0.f, d3 = 0.f;
            #pragma unroll
            for (int j = 0; j < 4; j++) {
                uint4 kk = kr[j];
                d0 = fmaf(q[8 * j],     bflo(kk.x), d0);
                d1 = fmaf(q[8 * j + 1], bfhi(kk.x), d1);
                d2 = fmaf(q[8 * j + 2], bflo(kk.y), d2);
                d3 = fmaf(q[8 * j + 3], bfhi(kk.y), d3);
                d0 = fmaf(q[8 * j + 4], bflo(kk.z), d0);
                d1 = fmaf(q[8 * j + 5], bfhi(kk.z), d1);
                d2 = fmaf(q[8 * j + 6], bflo(kk.w), d2);
                d3 = fmaf(q[8 * j + 7], bfhi(kk.w), d3);
            }
            float e = __expf((d0 + d1) + (d2 + d3));
            ssum += e;
            const uint4* vr = (const uint4*)(skv + t * KVU + 128 + h * 16);
            #pragma unroll
            for (int j = 0; j < 4; j++) {
                uint4 vv = vr[j];
                o[8 * j]     = fmaf(e, bflo(vv.x), o[8 * j]);
                o[8 * j + 1] = fmaf(e, bfhi(vv.x), o[8 * j + 1]);
                o[8 * j + 2] = fmaf(e, bflo(vv.y), o[8 * j + 2]);
                o[8 * j + 3] = fmaf(e, bfhi(vv.y), o[8 * j + 3]);
                o[8 * j + 4] = fmaf(e, bflo(vv.z), o[8 * j + 4]);
                o[8 * j + 5] = fmaf(e, bfhi(vv.z), o[8 * j + 5]);
                o[8 * j + 6] = fmaf(e, bflo(vv.w), o[8 * j + 6]);
                o[8 * j + 7] = fmaf(e, bfhi(vv.w), o[8 * j + 7]);
            }
        }
        float inv = 1.f / ssum;
        __nv_bfloat162* dst = (__nv_bfloat162*)(
            g_attn + ((size_t)w * SDIM + s) * CDIM + h * DHEAD);
        #pragma unroll
        for (int i = 0; i < 16; i++)
            dst[i] = __floats2bfloat162_rn(o[2 * i] * inv, o[2 * i + 1] * inv);
    }
}

// ---------------- bf16 mma.sync GEMM (m16n8k16, ldmatrix operands) ----------------
// EPI 0/2: bias(+gelu) in registers, bf16 stage (stride 68 words), uint4 copy out.
// EPI 1/3: fp32 stage + residual reader (unchanged).
#define CHUNK_K 64
#define SBF     72
#define SBF_B   (SBF * 2)
#define BUF_ELE (256 * SBF)
#define BUF_BYTES (BUF_ELE * 2)
#define GEMM_SMEM (2 * BUF_BYTES)
#define STW 68   /* bf16x2 words per staged row */

template<int KT, int NT, int EPI>
__global__ void __launch_bounds__(256) gemm_mma(
    const __nv_bfloat16* __restrict__ A, const __nv_bfloat16* __restrict__ B,
    const float* __restrict__ bias, const float* __restrict__ res,
    void* __restrict__ outp)
{
    extern __shared__ float smemf[];
    __nv_bfloat16* smem = (__nv_bfloat16*)smemf;
    const int tid = threadIdx.x;
    const int wid = tid >> 5, lane = tid & 31;
    const int g = lane >> 2, t = lane & 3;
    const int warp_m = wid & 1, warp_n = wid >> 1;
    const int n0 = blockIdx.x * 128;
    const int m0 = blockIdx.y * 128;
    const uint32_t sbase = smem_u32(smem);

    const int lm = lane >> 3;
    const int lr = lane & 7;
    const uint32_t a_off0 = (uint32_t)(warp_m * 64 + (lm & 1) * 8 + lr) * SBF_B
                          + (uint32_t)(lm >> 1) * 16;
    const uint32_t b_off0 = (uint32_t)(128 * SBF_B)
                          + (uint32_t)(warp_n * 32 + (lm >> 1) * 8 + lr) * SBF_B
                          + (uint32_t)(lm & 1) * 16;

    float acc[4][4][4];
    #pragma unroll
    for (int i = 0; i < 4; i++)
        #pragma unroll
        for (int j = 0; j < 4; j++)
            #pragma unroll
            for (int r = 0; r < 4; r++) acc[i][j][r] = 0.f;

    constexpr int KCH = KT / CHUNK_K;

    auto load_chunk = [&](int s, int kc) {
        uint32_t base = sbase + (uint32_t)s * BUF_BYTES;
        #pragma unroll
        for (int it = 0; it < 4; it++) {
            int idx = it * 256 + tid;
            int row = idx >> 3, seg = idx & 7;
            cp16(base + (uint32_t)(row * SBF_B + seg * 16),
                 A + (size_t)(m0 + row) * KT + kc * CHUNK_K + seg * 8);
        }
        #pragma unroll
        for (int it = 0; it < 4; it++) {
            int idx = it * 256 + tid;
            int row = idx >> 3, seg = idx & 7;
            cp16(base + (uint32_t)(128 * SBF_B + row * SBF_B + seg * 16),
                 B + (size_t)(n0 + row) * KT + kc * CHUNK_K + seg * 8);
        }
    };

    load_chunk(0, 0); CP_COMMIT();

    for (int kc = 0; kc < KCH; kc++) {
        int s = kc & 1;
        if (kc + 1 < KCH) {
            load_chunk((kc + 1) & 1, kc + 1); CP_COMMIT();
            CP_WAIT(1);
        } else {
            CP_WAIT(0);
        }
        __syncthreads();

        uint32_t abase = sbase + (uint32_t)s * BUF_BYTES + a_off0;
        uint32_t bbase = sbase + (uint32_t)s * BUF_BYTES + b_off0;

        #pragma unroll
        for (int ks = 0; ks < 4; ks++) {
            uint32_t kb = (uint32_t)ks * 32;
            uint32_t bf[4][2];
            ldsm_x4(bf[0][0], bf[0][1], bf[1][0], bf[1][1], bbase + kb);
            ldsm_x4(bf[2][0], bf[2][1], bf[3][0], bf[3][1],
                    bbase + kb + 16u * SBF_B);
            #pragma unroll
            for (int mt = 0; mt < 4; mt++) {
                uint32_t a0, a1, a2, a3;
                ldsm_x4(a0, a1, a2, a3, abase + kb + (uint32_t)mt * 16u * SBF_B);
                #pragma unroll
                for (int nt = 0; nt < 4; nt++)
                    mma_bf16(acc[mt][nt], a0, a1, a2, a3, bf[nt][0], bf[nt][1]);
            }
        }
        __syncthreads();
    }

    if (EPI == 0 || EPI == 2) {
        // --- bf16 epilogue: bias(+gelu) in regs -> bf16 stage -> uint4 copy ---
        uint32_t* stg16 = (uint32_t*)smemf;
        float bcol[4][2];
        #pragma unroll
        for (int nt = 0; nt < 4; nt++) {
            int col = warp_n * 32 + nt * 8 + 2 * t;
            bcol[nt][0] = bias[n0 + col];
            bcol[nt][1] = bias[n0 + col + 1];
        }
        #pragma unroll
        for (int mt = 0; mt < 4; mt++) {
            int row = warp_m * 64 + mt * 16 + g;
            #pragma unroll
            for (int nt = 0; nt < 4; nt++) {
                int colw = (warp_n * 32 + nt * 8 + 2 * t) >> 1;
                float v0 = acc[mt][nt][0] + bcol[nt][0];
                float v1 = acc[mt][nt][1] + bcol[nt][1];
                float v2 = acc[mt][nt][2] + bcol[nt][0];
                float v3 = acc[mt][nt][3] + bcol[nt][1];
                if (EPI == 2) {
                    v0 = gelu_fast(v0); v1 = gelu_fast(v1);
                    v2 = gelu_fast(v2); v3 = gelu_fast(v3);
                }
                __nv_bfloat162 p0 = __floats2bfloat162_rn(v0, v1);
                __nv_bfloat162 p1 = __floats2bfloat162_rn(v2, v3);
                stg16[row * STW + colw]       = *(uint32_t*)&p0;
                stg16[(row + 8) * STW + colw] = *(uint32_t*)&p1;
            }
        }
        __syncthreads();
        uint4* ob4 = (uint4*)outp;
        #pragma unroll
        for (int it = 0; it < 8; it++) {
            int i = it * 256 + tid;        // 2048 uint4 total
            int row = i >> 4, seg = i & 15;
            uint4 val = *(uint4*)(stg16 + row * STW + seg * 4);
            ob4[((size_t)(m0 + row) * NT + n0) / 8 + seg] = val;
        }
    } else {
        // --- fp32 epilogue with residual (proj / fc2) ---
        float* stg = smemf;
        #pragma unroll
        for (int mt = 0; mt < 4; mt++) {
            #pragma unroll
            for (int nt = 0; nt < 4; nt++) {
                int row = warp_m * 64 + mt * 16 + g;
                int col = warp_n * 32 + nt * 8 + 2 * t;
                stg[row * 132 + col]           = acc[mt][nt][0];
                stg[row * 132 + col + 1]       = acc[mt][nt][1];
                stg[(row + 8) * 132 + col]     = acc[mt][nt][2];
                stg[(row + 8) * 132 + col + 1] = acc[mt][nt][3];
            }
        }
        __syncthreads();

        int col = tid & 127;
        int r0  = tid >> 7;
        float bi = bias[n0 + col];
        float* of = (float*)outp;
        #pragma unroll 4
        for (int i = 0; i < 64; i++) {
            int r = r0 + i * 2;
            int gr = m0 + r;
            float v = stg[r * 132 + col] + bi + res[(size_t)gr * NT + n0 + col];
            if (EPI == 3) {
                int w = gr / SDIM, sx = gr - (gr / SDIM) * SDIM;
                size_t dst = (sx == 0)
                    ? ((size_t)NTOK * CDIM + (size_t)w * CDIM + n0 + col)
                    : (((size_t)(w * KTOK + sx - 1)) * CDIM + n0 + col);
                of[dst] = v;
            } else {
                of[(size_t)gr * NT + n0 + col] = v;
            }
        }
    }
}

// ---------------------------------------------------------------------------
extern "C" void kernel_launch(void* const* d_in, const int* in_sizes, int n_in,
                              void* d_out, int out_size)
{
    const float* data     = (const float*)d_in[0];
    const float* relay    = (const float*)d_in[1];
    const int*   neigh    = (const int*)  d_in[2];
    const float* cpe_w    = (const float*)d_in[3];
    const float* bn_gamma = (const float*)d_in[4];
    const float* bn_beta  = (const float*)d_in[5];
    const float* bn_mean  = (const float*)d_in[6];
    const float* bn_var   = (const float*)d_in[7];
    const float* norm1_g  = (const float*)d_in[8];
    const float* norm1_b  = (const float*)d_in[9];
    const float* qkv_w    = (const float*)d_in[10];
    const float* qkv_b    = (const float*)d_in[11];
    const float* proj_w   = (const float*)d_in[12];
    const float* proj_b   = (const float*)d_in[13];
    const float* norm2_g  = (const float*)d_in[14];
    const float* norm2_b  = (const float*)d_in[15];
    const float* fc1_w    = (const float*)d_in[16];
    const float* fc1_b    = (const float*)d_in[17];
    const float* fc2_w    = (const float*)d_in[18];
    const float* fc2_b    = (const float*)d_in[19];
    float* out = (float*)d_out;

    static bool inited = false;
    static __nv_bfloat16 *p_h, *p_h2, *p_qkv, *p_attn, *p_f1;
    static __nv_bfloat16 *p_wq, *p_wp, *p_w1, *p_w2;
    static float *p_x, *p_x2;
    if (!inited) {
        cudaFuncSetAttribute(gemm_mma<256, 768, 0>,
            cudaFuncAttributeMaxDynamicSharedMemorySize, GEMM_SMEM);
        cudaFuncSetAttribute(gemm_mma<256, 256, 1>,
            cudaFuncAttributeMaxDynamicSharedMemorySize, GEMM_SMEM);
        cudaFuncSetAttribute(gemm_mma<256, 1024, 2>,
            cudaFuncAttributeMaxDynamicSharedMemorySize, GEMM_SMEM);
        cudaFuncSetAttribute(gemm_mma<1024, 256, 3>,
            cudaFuncAttributeMaxDynamicSharedMemorySize, GEMM_SMEM);
        cudaFuncSetAttribute(attn_kernel,
            cudaFuncAttributeMaxDynamicSharedMemorySize, ATTN_SMEM);
        void* t;
        cudaGetSymbolAddress(&t, g_h);    p_h    = (__nv_bfloat16*)t;
        cudaGetSymbolAddress(&t, g_h2);   p_h2   = (__nv_bfloat16*)t;
        cudaGetSymbolAddress(&t, g_qkv);  p_qkv  = (__nv_bfloat16*)t;
        cudaGetSymbolAddress(&t, g_attn); p_attn = (__nv_bfloat16*)t;
        cudaGetSymbolAddress(&t, g_f1);   p_f1   = (__nv_bfloat16*)t;
        cudaGetSymbolAddress(&t, g_x);    p_x    = (float*)t;
        cudaGetSymbolAddress(&t, g_x2);   p_x2   = (float*)t;
        cudaGetSymbolAddress(&t, g_wq);   p_wq   = (__nv_bfloat16*)t;
        cudaGetSymbolAddress(&t, g_wp);   p_wp   = (__nv_bfloat16*)t;
        cudaGetSymbolAddress(&t, g_w1);   p_w1   = (__nv_bfloat16*)t;
        cudaGetSymbolAddress(&t, g_w2);   p_w2   = (__nv_bfloat16*)t;
        inited = true;
    }

    convert_data_kernel<<<NTOK * CDIM / 8 / 256, 256>>>(data);
    transpose_all_kernel<<<786432 / 256, 256>>>(qkv_w, proj_w, fc1_w, fc2_w);

    cpe_ln1_kernel<<<RTOT / 8, 256>>>(data, relay, neigh, cpe_w,
                                      bn_gamma, bn_beta, bn_mean, bn_var,
                                      norm1_g, norm1_b);

    const int GB = RTOT / 128;  // 1056
    gemm_mma<256, 768, 0><<<dim3(6, GB), 256, GEMM_SMEM>>>(p_h, p_wq, qkv_b, nullptr, p_qkv);

    attn_kernel<<<W_WIN, 288, ATTN_SMEM>>>();

    gemm_mma<256, 256, 1><<<dim3(2, GB), 256, GEMM_SMEM>>>(p_attn, p_wp, proj_b, p_x, p_x2);

    ln2_kernel<<<RTOT / 8, 256>>>(norm2_g, norm2_b);

    gemm_mma<256, 1024, 2><<<dim3(8, GB), 256, GEMM_SMEM>>>(p_h2, p_w1, fc1_b, nullptr, p_f1);

    gemm_mma<1024, 256, 3><<<dim3(2, GB), 256, GEMM_SMEM>>>(p_f1, p_w2, fc2_b, p_x2, out);
}

// round 16
// speedup vs baseline: 1.3174x; 1.0645x over previous
#include <cuda_runtime.h>
#include <cuda_bf16.h>
#include <math.h>
#include <stdint.h>

#define W_WIN 4096
#define KTOK  32
#define CDIM  256
#define HEADS 8
#define DHEAD 32
#define NTOK  (W_WIN * KTOK)
#define KC    27
#define SDIM  33
#define RTOT  (W_WIN * SDIM)
#define EPS   1e-5f

// ---------------- device scratch ----------------
__device__ float g_x [(size_t)RTOT * CDIM];
__device__ float g_x2[(size_t)RTOT * CDIM];
__device__ __nv_bfloat16 g_databf[(size_t)NTOK * CDIM];
__device__ __nv_bfloat16 g_h   [(size_t)RTOT * CDIM];
__device__ __nv_bfloat16 g_h2  [(size_t)RTOT * CDIM];
__device__ __nv_bfloat16 g_qkv [(size_t)RTOT * 3 * CDIM];
__device__ __nv_bfloat16 g_attn[(size_t)RTOT * CDIM];
__device__ __nv_bfloat16 g_f1  [(size_t)RTOT * 1024];
__device__ __nv_bfloat16 g_wq[768 * 256];
__device__ __nv_bfloat16 g_wp[256 * 256];
__device__ __nv_bfloat16 g_w1[1024 * 256];
__device__ __nv_bfloat16 g_w2[256 * 1024];

// ---------------- helpers ----------------
__device__ __forceinline__ uint32_t smem_u32(const void* p) {
    uint32_t a;
    asm("{ .reg .u64 t; cvta.to.shared.u64 t, %1; cvt.u32.u64 %0, t; }"
        : "=r"(a) : "l"(p));
    return a;
}
__device__ __forceinline__ void cp16(uint32_t dst, const void* src) {
    asm volatile("cp.async.ca.shared.global [%0], [%1], 16;" :: "r"(dst), "l"(src));
}
#define CP_COMMIT() asm volatile("cp.async.commit_group;" ::: "memory")
#define CP_WAIT(n)  asm volatile("cp.async.wait_group %0;" :: "n"(n) : "memory")

__device__ __forceinline__ void mma_bf16(float d[4], uint32_t a0, uint32_t a1,
                                         uint32_t a2, uint32_t a3,
                                         uint32_t b0, uint32_t b1) {
    asm volatile(
        "mma.sync.aligned.m16n8k16.row.col.f32.bf16.bf16.f32 "
        "{%0,%1,%2,%3}, {%4,%5,%6,%7}, {%8,%9}, {%0,%1,%2,%3};"
        : "+f"(d[0]), "+f"(d[1]), "+f"(d[2]), "+f"(d[3])
        : "r"(a0), "r"(a1), "r"(a2), "r"(a3), "r"(b0), "r"(b1));
}
__device__ __forceinline__ void ldsm_x4(uint32_t& r0, uint32_t& r1,
                                        uint32_t& r2, uint32_t& r3, uint32_t a) {
    asm volatile("ldmatrix.sync.aligned.m8n8.x4.shared.b16 {%0,%1,%2,%3}, [%4];"
                 : "=r"(r0), "=r"(r1), "=r"(r2), "=r"(r3) : "r"(a));
}
__device__ __forceinline__ float bflo(uint32_t u) { return __uint_as_float(u << 16); }
__device__ __forceinline__ float bfhi(uint32_t u) { return __uint_as_float(u & 0xffff0000u); }

__device__ __forceinline__ float gelu_fast(float v) {
    float x3 = v * v * v;
    float u = 0.7978845608028654f * (v + 0.044715f * x3);
    float th;
    asm("tanh.approx.f32 %0, %1;" : "=f"(th) : "f"(u));
    return 0.5f * v * (1.f + th);
}

// ---------------- data -> bf16 mirror ----------------
__global__ void __launch_bounds__(256) convert_data_kernel(
    const float* __restrict__ data)
{
    int i = blockIdx.x * 256 + threadIdx.x;
    const float4* s = (const float4*)data + (size_t)i * 2;
    float4 a = s[0], b = s[1];
    __nv_bfloat162 p0 = __floats2bfloat162_rn(a.x, a.y);
    __nv_bfloat162 p1 = __floats2bfloat162_rn(a.z, a.w);
    __nv_bfloat162 p2 = __floats2bfloat162_rn(b.x, b.y);
    __nv_bfloat162 p3 = __floats2bfloat162_rn(b.z, b.w);
    uint4 o;
    o.x = *(uint32_t*)&p0; o.y = *(uint32_t*)&p1;
    o.z = *(uint32_t*)&p2; o.w = *(uint32_t*)&p3;
    ((uint4*)g_databf)[i] = o;
}

// ---------------- fused weight transpose -> bf16 (all four) ----------------
__global__ void transpose_all_kernel(
    const float* __restrict__ qkv_w, const float* __restrict__ proj_w,
    const float* __restrict__ fc1_w, const float* __restrict__ fc2_w)
{
    int i = blockIdx.x * 256 + threadIdx.x;
    if (i < 196608) {
        int n = i / 256, k = i - n * 256;
        g_wq[i] = __float2bfloat16(qkv_w[(size_t)k * 768 + n]);
    } else if (i < 262144) {
        int j = i - 196608;
        int n = j / 256, k = j - n * 256;
        g_wp[j] = __float2bfloat16(proj_w[(size_t)k * 256 + n]);
    } else if (i < 524288) {
        int j = i - 262144;
        int n = j / 256, k = j - n * 256;
        g_w1[j] = __float2bfloat16(fc1_w[(size_t)k * 1024 + n]);
    } else {
        int j = i - 524288;
        int n = j / 1024, k = j - n * 1024;
        g_w2[j] = __float2bfloat16(fc2_w[(size_t)k * 256 + n]);
    }
}

// ---------------- fused CPE + build x + LN1 (bf16 gather) ----------------
__global__ void __launch_bounds__(256) cpe_ln1_kernel(
    const float* __restrict__ data, const float* __restrict__ relay,
    const int* __restrict__ neigh, const float* __restrict__ cpe_w,
    const float* __restrict__ bn_gamma, const float* __restrict__ bn_beta,
    const float* __restrict__ bn_mean, const float* __restrict__ bn_var,
    const float* __restrict__ g, const float* __restrict__ b)
{
    int warp = threadIdx.x >> 5, lane = threadIdx.x & 31;
    int gr = blockIdx.x * 8 + warp;
    int w = gr / SDIM, s = gr - w * SDIM;

    float v[8];
    if (s == 0) {
        const float4* src = (const float4*)(relay + (size_t)w * CDIM) + lane * 2;
        float4 a = src[0], bb4 = src[1];
        v[0] = a.x; v[1] = a.y; v[2] = a.z; v[3] = a.w;
        v[4] = bb4.x; v[5] = bb4.y; v[6] = bb4.z; v[7] = bb4.w;
    } else {
        int n = w * KTOK + s - 1;
        int nb = (lane < KC) ? neigh[(size_t)n * KC + lane] : 0;
        float acc[8];
        #pragma unroll
        for (int i = 0; i < 8; i++) acc[i] = 0.f;
        #pragma unroll
        for (int k = 0; k < KC; k++) {
            int idx = __shfl_sync(0xffffffffu, nb, k);
            uint4 d4 = ((const uint4*)g_databf)[(size_t)idx * 32 + lane];
            const float4* wr = (const float4*)(cpe_w + k * CDIM) + lane * 2;
            float4 w0 = wr[0], w1 = wr[1];
            acc[0] = fmaf(bflo(d4.x), w0.x, acc[0]);
            acc[1] = fmaf(bfhi(d4.x), w0.y, acc[1]);
            acc[2] = fmaf(bflo(d4.y), w0.z, acc[2]);
            acc[3] = fmaf(bfhi(d4.y), w0.w, acc[3]);
            acc[4] = fmaf(bflo(d4.z), w1.x, acc[4]);
            acc[5] = fmaf(bfhi(d4.z), w1.y, acc[5]);
            acc[6] = fmaf(bflo(d4.w), w1.z, acc[6]);
            acc[7] = fmaf(bfhi(d4.w), w1.w, acc[7]);
        }
        const float4* dr = (const float4*)(data + (size_t)n * CDIM) + lane * 2;
        const float4* bm = (const float4*)bn_mean + lane * 2;
        const float4* bv = (const float4*)bn_var + lane * 2;
        const float4* bg = (const float4*)bn_gamma + lane * 2;
        const float4* bb = (const float4*)bn_beta + lane * 2;
        #pragma unroll
        for (int i = 0; i < 2; i++) {
            float4 d = dr[i], m = bm[i], va = bv[i], ga = bg[i], be = bb[i];
            v[4*i]   = d.x + (acc[4*i]   - m.x) * rsqrtf(va.x + EPS) * ga.x + be.x;
            v[4*i+1] = d.y + (acc[4*i+1] - m.y) * rsqrtf(va.y + EPS) * ga.y + be.y;
            v[4*i+2] = d.z + (acc[4*i+2] - m.z) * rsqrtf(va.z + EPS) * ga.z + be.z;
            v[4*i+3] = d.w + (acc[4*i+3] - m.w) * rsqrtf(va.w + EPS) * ga.w + be.w;
        }
    }

    float sm = 0.f, s2 = 0.f;
    #pragma unroll
    for (int i = 0; i < 8; i++) { sm += v[i]; s2 = fmaf(v[i], v[i], s2); }
    #pragma unroll
    for (int o = 16; o; o >>= 1) {
        sm += __shfl_xor_sync(0xffffffffu, sm, o);
        s2 += __shfl_xor_sync(0xffffffffu, s2, o);
    }
    float mu = sm * (1.f / CDIM);
    float rs = rsqrtf(s2 * (1.f / CDIM) - mu * mu + EPS);

    float4* xo = (float4*)(g_x + (size_t)gr * CDIM) + lane * 2;
    xo[0] = make_float4(v[0], v[1], v[2], v[3]);
    xo[1] = make_float4(v[4], v[5], v[6], v[7]);

    const float4* gg = (const float4*)g + lane * 2;
    const float4* gb = (const float4*)b + lane * 2;
    float hh[8];
    #pragma unroll
    for (int i = 0; i < 2; i++) {
        float4 ga = gg[i], be = gb[i];
        hh[4*i]   = (v[4*i]   - mu) * rs * ga.x + be.x;
        hh[4*i+1] = (v[4*i+1] - mu) * rs * ga.y + be.y;
        hh[4*i+2] = (v[4*i+2] - mu) * rs * ga.z + be.z;
        hh[4*i+3] = (v[4*i+3] - mu) * rs * ga.w + be.w;
    }
    __nv_bfloat162 p0 = __floats2bfloat162_rn(hh[0], hh[1]);
    __nv_bfloat162 p1 = __floats2bfloat162_rn(hh[2], hh[3]);
    __nv_bfloat162 p2 = __floats2bfloat162_rn(hh[4], hh[5]);
    __nv_bfloat162 p3 = __floats2bfloat162_rn(hh[6], hh[7]);
    uint4 ho;
    ho.x = *(uint32_t*)&p0; ho.y = *(uint32_t*)&p1;
    ho.z = *(uint32_t*)&p2; ho.w = *(uint32_t*)&p3;
    ((uint4*)(g_h + (size_t)gr * CDIM))[lane] = ho;
}

// ---------------- LN2: g_x2 (fp32) -> g_h2 (bf16) ----------------
__global__ void __launch_bounds__(256) ln2_kernel(
    const float* __restrict__ g, const float* __restrict__ b)
{
    int warp = threadIdx.x >> 5, lane = threadIdx.x & 31;
    int gr = blockIdx.x * 8 + warp;
    const float2* src = (const float2*)(g_x2 + (size_t)gr * CDIM);
    float2 v[4];
    float sm = 0.f, s2 = 0.f;
    #pragma unroll
    for (int i = 0; i < 4; i++) {
        v[i] = src[lane + i * 32];
        sm += v[i].x + v[i].y;
        s2 = fmaf(v[i].x, v[i].x, fmaf(v[i].y, v[i].y, s2));
    }
    #pragma unroll
    for (int o = 16; o; o >>= 1) {
        sm += __shfl_xor_sync(0xffffffffu, sm, o);
        s2 += __shfl_xor_sync(0xffffffffu, s2, o);
    }
    float mu = sm * (1.f / CDIM);
    float rs = rsqrtf(s2 * (1.f / CDIM) - mu * mu + EPS);
    uint32_t* ho = (uint32_t*)(g_h2 + (size_t)gr * CDIM);
    const float2* gg = (const float2*)g;
    const float2* gb = (const float2*)b;
    #pragma unroll
    for (int i = 0; i < 4; i++) {
        int c = lane + i * 32;
        float2 ga = gg[c], be = gb[c];
        __nv_bfloat162 h = __floats2bfloat162_rn(
            (v[i].x - mu) * rs * ga.x + be.x,
            (v[i].y - mu) * rs * ga.y + be.y);
        ho[c] = *(uint32_t*)&h;
    }
}

// ---------------- attention v7: 2 threads per (head, query) ----------------
// block = window, 544 threads; pair p = tid>>1 (264 valid), half = tid&1.
// Each thread: q[16]/o[16] (half the head dims), 16-dim partial dot,
// shfl_xor(.,1) to combine, identical e both halves.
// Tail threads (p >= 264) run with h clamped to 7 (valid reads), no store.
#define KVU 264
#define ATTN_SMEM (SDIM * KVU * 4)

__global__ void __launch_bounds__(544, 2) attn_kernel()
{
    extern __shared__ uint32_t skv[];
    int w = blockIdx.x, tid = threadIdx.x;

    const uint4* src4 = (const uint4*)(g_qkv + (size_t)w * SDIM * 768);
    for (int i = tid; i < SDIM * 64; i += 544) {
        int r = i >> 6, c = i & 63;
        uint4 q4 = src4[r * 96 + 32 + c];
        *(uint4*)(skv + r * KVU + c * 4) = q4;
    }
    __syncthreads();

    int p = tid >> 1, half = tid & 1;
    int h = p / SDIM;
    int s = p - h * SDIM;
    if (h > 7) { h = 7; }                 // tail threads: valid reads, no store
    const float scale = 0.17677669529663687f;
    const int doff = h * 16 + half * 8;   // word offset of this thread's 16 dims

    float q[16];
    {
        const uint32_t* qsrc = (const uint32_t*)(
            g_qkv + ((size_t)w * SDIM + (s < SDIM ? s : 0)) * 768) + doff;
        #pragma unroll
        for (int i = 0; i < 8; i++) {
            uint32_t pq = qsrc[i];
            q[2 * i]     = bflo(pq) * scale;
            q[2 * i + 1] = bfhi(pq) * scale;
        }
    }

    float o[16];
    #pragma unroll
    for (int d = 0; d < 16; d++) o[d] = 0.f;
    float ssum = 0.f;

    #pragma unroll 1
    for (int t = 0; t < SDIM; t++) {
        const uint4* kr = (const uint4*)(skv + t * KVU + doff);
        uint4 k0 = kr[0], k1 = kr[1];
        float d0 = 0.f, d1 = 0.f, d2 = 0.f, d3 = 0.f;
        d0 = fmaf(q[0],  bflo(k0.x), d0);
        d1 = fmaf(q[1],  bfhi(k0.x), d1);
        d2 = fmaf(q[2],  bflo(k0.y), d2);
        d3 = fmaf(q[3],  bfhi(k0.y), d3);
        d0 = fmaf(q[4],  bflo(k0.z), d0);
        d1 = fmaf(q[5],  bfhi(k0.z), d1);
        d2 = fmaf(q[6],  bflo(k0.w), d2);
        d3 = fmaf(q[7],  bfhi(k0.w), d3);
        d0 = fmaf(q[8],  bflo(k1.x), d0);
        d1 = fmaf(q[9],  bfhi(k1.x), d1);
        d2 = fmaf(q[10], bflo(k1.y), d2);
        d3 = fmaf(q[11], bfhi(k1.y), d3);
        d0 = fmaf(q[12], bflo(k1.z), d0);
        d1 = fmaf(q[13], bfhi(k1.z), d1);
        d2 = fmaf(q[14], bflo(k1.w), d2);
        d3 = fmaf(q[15], bfhi(k1.w), d3);
        float dhalf = (d0 + d1) + (d2 + d3);
        float dot = dhalf + __shfl_xor_sync(0xffffffffu, dhalf, 1);
        float e = __expf(dot);
        ssum += e;

        const uint4* vr = (const uint4*)(skv + t * KVU + 128 + doff);
        uint4 v0 = vr[0], v1 = vr[1];
        o[0]  = fmaf(e, bflo(v0.x), o[0]);
        o[1]  = fmaf(e, bfhi(v0.x), o[1]);
        o[2]  = fmaf(e, bflo(v0.y), o[2]);
        o[3]  = fmaf(e, bfhi(v0.y), o[3]);
        o[4]  = fmaf(e, bflo(v0.z), o[4]);
        o[5]  = fmaf(e, bfhi(v0.z), o[5]);
        o[6]  = fmaf(e, bflo(v0.w), o[6]);
        o[7]  = fmaf(e, bfhi(v0.w), o[7]);
        o[8]  = fmaf(e, bflo(v1.x), o[8]);
        o[9]  = fmaf(e, bfhi(v1.x), o[9]);
        o[10] = fmaf(e, bflo(v1.y), o[10]);
        o[11] = fmaf(e, bfhi(v1.y), o[11]);
        o[12] = fmaf(e, bflo(v1.z), o[12]);
        o[13] = fmaf(e, bfhi(v1.z), o[13]);
        o[14] = fmaf(e, bflo(v1.w), o[14]);
        o[15] = fmaf(e, bfhi(v1.w), o[15]);
    }

    if (tid < HEADS * SDIM * 2) {
        float inv = 1.f / ssum;
        uint32_t pk[8];
        #pragma unroll
        for (int i = 0; i < 8; i++) {
            __nv_bfloat162 pp = __floats2bfloat162_rn(o[2*i] * inv, o[2*i+1] * inv);
            pk[i] = *(uint32_t*)&pp;
        }
        uint4* dst = (uint4*)((uint32_t*)(
            g_attn + ((size_t)w * SDIM + s) * CDIM + h * DHEAD) + half * 8);
        dst[0] = make_uint4(pk[0], pk[1], pk[2], pk[3]);
        dst[1] = make_uint4(pk[4], pk[5], pk[6], pk[7]);
    }
}

// ---------------- bf16 mma.sync GEMM (m16n8k16, ldmatrix operands) ----------------
#define CHUNK_K 64
#define SBF     72
#define SBF_B   (SBF * 2)
#define BUF_ELE (256 * SBF)
#define BUF_BYTES (BUF_ELE * 2)
#define GEMM_SMEM (2 * BUF_BYTES)
#define STW 68

template<int KT, int NT, int EPI>
__global__ void __launch_bounds__(256) gemm_mma(
    const __nv_bfloat16* __restrict__ A, const __nv_bfloat16* __restrict__ B,
    const float* __restrict__ bias, const float* __restrict__ res,
    void* __restrict__ outp)
{
    extern __shared__ float smemf[];
    __nv_bfloat16* smem = (__nv_bfloat16*)smemf;
    const int tid = threadIdx.x;
    const int wid = tid >> 5, lane = tid & 31;
    const int g = lane >> 2, t = lane & 3;
    const int warp_m = wid & 1, warp_n = wid >> 1;
    const int n0 = blockIdx.x * 128;
    const int m0 = blockIdx.y * 128;
    const uint32_t sbase = smem_u32(smem);

    const int lm = lane >> 3;
    const int lr = lane & 7;
    const uint32_t a_off0 = (uint32_t)(warp_m * 64 + (lm & 1) * 8 + lr) * SBF_B
                          + (uint32_t)(lm >> 1) * 16;
    const uint32_t b_off0 = (uint32_t)(128 * SBF_B)
                          + (uint32_t)(warp_n * 32 + (lm >> 1) * 8 + lr) * SBF_B
                          + (uint32_t)(lm & 1) * 16;

    float acc[4][4][4];
    #pragma unroll
    for (int i = 0; i < 4; i++)
        #pragma unroll
        for (int j = 0; j < 4; j++)
            #pragma unroll
            for (int r = 0; r < 4; r++) acc[i][j][r] = 0.f;

    constexpr int KCH = KT / CHUNK_K;

    auto load_chunk = [&](int s, int kc) {
        uint32_t base = sbase + (uint32_t)s * BUF_BYTES;
        #pragma unroll
        for (int it = 0; it < 4; it++) {
            int idx = it * 256 + tid;
            int row = idx >> 3, seg = idx & 7;
            cp16(base + (uint32_t)(row * SBF_B + seg * 16),
                 A + (size_t)(m0 + row) * KT + kc * CHUNK_K + seg * 8);
        }
        #pragma unroll
        for (int it = 0; it < 4; it++) {
            int idx = it * 256 + tid;
            int row = idx >> 3, seg = idx & 7;
            cp16(base + (uint32_t)(128 * SBF_B + row * SBF_B + seg * 16),
                 B + (size_t)(n0 + row) * KT + kc * CHUNK_K + seg * 8);
        }
    };

    load_chunk(0, 0); CP_COMMIT();

    for (int kc = 0; kc < KCH; kc++) {
        int s = kc & 1;
        if (kc + 1 < KCH) {
            load_chunk((kc + 1) & 1, kc + 1); CP_COMMIT();
            CP_WAIT(1);
        } else {
            CP_WAIT(0);
        }
        __syncthreads();

        uint32_t abase = sbase + (uint32_t)s * BUF_BYTES + a_off0;
        uint32_t bbase = sbase + (uint32_t)s * BUF_BYTES + b_off0;

        #pragma unroll
        for (int ks = 0; ks < 4; ks++) {
            uint32_t kb = (uint32_t)ks * 32;
            uint32_t bf[4][2];
            ldsm_x4(bf[0][0], bf[0][1], bf[1][0], bf[1][1], bbase + kb);
            ldsm_x4(bf[2][0], bf[2][1], bf[3][0], bf[3][1],
                    bbase + kb + 16u * SBF_B);
            #pragma unroll
            for (int mt = 0; mt < 4; mt++) {
                uint32_t a0, a1, a2, a3;
                ldsm_x4(a0, a1, a2, a3, abase + kb + (uint32_t)mt * 16u * SBF_B);
                #pragma unroll
                for (int nt = 0; nt < 4; nt++)
                    mma_bf16(acc[mt][nt], a0, a1, a2, a3, bf[nt][0], bf[nt][1]);
            }
        }
        __syncthreads();
    }

    if (EPI == 0 || EPI == 2) {
        uint32_t* stg16 = (uint32_t*)smemf;
        float bcol[4][2];
        #pragma unroll
        for (int nt = 0; nt < 4; nt++) {
            int col = warp_n * 32 + nt * 8 + 2 * t;
            bcol[nt][0] = bias[n0 + col];
            bcol[nt][1] = bias[n0 + col + 1];
        }
        #pragma unroll
        for (int mt = 0; mt < 4; mt++) {
            int row = warp_m * 64 + mt * 16 + g;
            #pragma unroll
            for (int nt = 0; nt < 4; nt++) {
                int colw = (warp_n * 32 + nt * 8 + 2 * t) >> 1;
                float v0 = acc[mt][nt][0] + bcol[nt][0];
                float v1 = acc[mt][nt][1] + bcol[nt][1];
                float v2 = acc[mt][nt][2] + bcol[nt][0];
                float v3 = acc[mt][nt][3] + bcol[nt][1];
                if (EPI == 2) {
                    v0 = gelu_fast(v0); v1 = gelu_fast(v1);
                    v2 = gelu_fast(v2); v3 = gelu_fast(v3);
                }
                __nv_bfloat162 p0 = __floats2bfloat162_rn(v0, v1);
                __nv_bfloat162 p1 = __floats2bfloat162_rn(v2, v3);
                stg16[row * STW + colw]       = *(uint32_t*)&p0;
                stg16[(row + 8) * STW + colw] = *(uint32_t*)&p1;
            }
        }
        __syncthreads();
        uint4* ob4 = (uint4*)outp;
        #pragma unroll
        for (int it = 0; it < 8; it++) {
            int i = it * 256 + tid;
            int row = i >> 4, seg = i & 15;
            uint4 val = *(uint4*)(stg16 + row * STW + seg * 4);
            ob4[((size_t)(m0 + row) * NT + n0) / 8 + seg] = val;
        }
    } else {
        float* stg = smemf;
        #pragma unroll
        for (int mt = 0; mt < 4; mt++) {
            #pragma unroll
            for (int nt = 0; nt < 4; nt++) {
                int row = warp_m * 64 + mt * 16 + g;
                int col = warp_n * 32 + nt * 8 + 2 * t;
                stg[row * 132 + col]           = acc[mt][nt][0];
                stg[row * 132 + col + 1]       = acc[mt][nt][1];
                stg[(row + 8) * 132 + col]     = acc[mt][nt][2];
                stg[(row + 8) * 132 + col + 1] = acc[mt][nt][3];
            }
        }
        __syncthreads();

        int col = tid & 127;
        int r0  = tid >> 7;
        float bi = bias[n0 + col];
        float* of = (float*)outp;
        #pragma unroll 4
        for (int i = 0; i < 64; i++) {
            int r = r0 + i * 2;
            int gr = m0 + r;
            float v = stg[r * 132 + col] + bi + res[(size_t)gr * NT + n0 + col];
            if (EPI == 3) {
                int w = gr / SDIM, sx = gr - (gr / SDIM) * SDIM;
                size_t dst = (sx == 0)
                    ? ((size_t)NTOK * CDIM + (size_t)w * CDIM + n0 + col)
                    : (((size_t)(w * KTOK + sx - 1)) * CDIM + n0 + col);
                of[dst] = v;
            } else {
                of[(size_t)gr * NT + n0 + col] = v;
            }
        }
    }
}

// ---------------------------------------------------------------------------
extern "C" void kernel_launch(void* const* d_in, const int* in_sizes, int n_in,
                              void* d_out, int out_size)
{
    const float* data     = (const float*)d_in[0];
    const float* relay    = (const float*)d_in[1];
    const int*   neigh    = (const int*)  d_in[2];
    const float* cpe_w    = (const float*)d_in[3];
    const float* bn_gamma = (const float*)d_in[4];
    const float* bn_beta  = (const float*)d_in[5];
    const float* bn_mean  = (const float*)d_in[6];
    const float* bn_var   = (const float*)d_in[7];
    const float* norm1_g  = (const float*)d_in[8];
    const float* norm1_b  = (const float*)d_in[9];
    const float* qkv_w    = (const float*)d_in[10];
    const float* qkv_b    = (const float*)d_in[11];
    const float* proj_w   = (const float*)d_in[12];
    const float* proj_b   = (const float*)d_in[13];
    const float* norm2_g  = (const float*)d_in[14];
    const float* norm2_b  = (const float*)d_in[15];
    const float* fc1_w    = (const float*)d_in[16];
    const float* fc1_b    = (const float*)d_in[17];
    const float* fc2_w    = (const float*)d_in[18];
    const float* fc2_b    = (const float*)d_in[19];
    float* out = (float*)d_out;

    static bool inited = false;
    static __nv_bfloat16 *p_h, *p_h2, *p_qkv, *p_attn, *p_f1;
    static __nv_bfloat16 *p_wq, *p_wp, *p_w1, *p_w2;
    static float *p_x, *p_x2;
    if (!inited) {
        cudaFuncSetAttribute(gemm_mma<256, 768, 0>,
            cudaFuncAttributeMaxDynamicSharedMemorySize, GEMM_SMEM);
        cudaFuncSetAttribute(gemm_mma<256, 256, 1>,
            cudaFuncAttributeMaxDynamicSharedMemorySize, GEMM_SMEM);
        cudaFuncSetAttribute(gemm_mma<256, 1024, 2>,
            cudaFuncAttributeMaxDynamicSharedMemorySize, GEMM_SMEM);
        cudaFuncSetAttribute(gemm_mma<1024, 256, 3>,
            cudaFuncAttributeMaxDynamicSharedMemorySize, GEMM_SMEM);
        cudaFuncSetAttribute(attn_kernel,
            cudaFuncAttributeMaxDynamicSharedMemorySize, ATTN_SMEM);
        void* t;
        cudaGetSymbolAddress(&t, g_h);    p_h    = (__nv_bfloat16*)t;
        cudaGetSymbolAddress(&t, g_h2);   p_h2   = (__nv_bfloat16*)t;
        cudaGetSymbolAddress(&t, g_qkv);  p_qkv  = (__nv_bfloat16*)t;
        cudaGetSymbolAddress(&t, g_attn); p_attn = (__nv_bfloat16*)t;
        cudaGetSymbolAddress(&t, g_f1);   p_f1   = (__nv_bfloat16*)t;
        cudaGetSymbolAddress(&t, g_x);    p_x    = (float*)t;
        cudaGetSymbolAddress(&t, g_x2);   p_x2   = (float*)t;
        cudaGetSymbolAddress(&t, g_wq);   p_wq   = (__nv_bfloat16*)t;
        cudaGetSymbolAddress(&t, g_wp);   p_wp   = (__nv_bfloat16*)t;
        cudaGetSymbolAddress(&t, g_w1);   p_w1   = (__nv_bfloat16*)t;
        cudaGetSymbolAddress(&t, g_w2);   p_w2   = (__nv_bfloat16*)t;
        inited = true;
    }

    convert_data_kernel<<<NTOK * CDIM / 8 / 256, 256>>>(data);
    transpose_all_kernel<<<786432 / 256, 256>>>(qkv_w, proj_w, fc1_w, fc2_w);

    cpe_ln1_kernel<<<RTOT / 8, 256>>>(data, relay, neigh, cpe_w,
                                      bn_gamma, bn_beta, bn_mean, bn_var,
                                      norm1_g, norm1_b);

    const int GB = RTOT / 128;  // 1056
    gemm_mma<256, 768, 0><<<dim3(6, GB), 256, GEMM_SMEM>>>(p_h, p_wq, qkv_b, nullptr, p_qkv);

    attn_kernel<<<W_WIN, 544, ATTN_SMEM>>>();

    gemm_mma<256, 256, 1><<<dim3(2, GB), 256, GEMM_SMEM>>>(p_attn, p_wp, proj_b, p_x, p_x2);

    ln2_kernel<<<RTOT / 8, 256>>>(norm2_g, norm2_b);

    gemm_mma<256, 1024, 2><<<dim3(8, GB), 256, GEMM_SMEM>>>(p_h2, p_w1, fc1_b, nullptr, p_f1);

    gemm_mma<1024, 256, 3><<<dim3(2, GB), 256, GEMM_SMEM>>>(p_f1, p_w2, fc2_b, p_x2, out);
}

// round 17
// speedup vs baseline: 1.3439x; 1.0201x over previous
#include <cuda_runtime.h>
#include <cuda_bf16.h>
#include <math.h>
#include <stdint.h>

#define W_WIN 4096
#define KTOK  32
#define CDIM  256
#define HEADS 8
#define DHEAD 32
#define NTOK  (W_WIN * KTOK)
#define KC    27
#define SDIM  33
#define RTOT  (W_WIN * SDIM)
#define EPS   1e-5f

// ---------------- device scratch ----------------
__device__ float g_x [(size_t)RTOT * CDIM];
__device__ float g_x2[(size_t)RTOT * CDIM];
__device__ __nv_bfloat16 g_databf[(size_t)NTOK * CDIM];
__device__ __nv_bfloat16 g_h   [(size_t)RTOT * CDIM];
__device__ __nv_bfloat16 g_h2  [(size_t)RTOT * CDIM];
__device__ __nv_bfloat16 g_qkv [(size_t)RTOT * 3 * CDIM];
__device__ __nv_bfloat16 g_attn[(size_t)RTOT * CDIM];
__device__ __nv_bfloat16 g_f1  [(size_t)RTOT * 1024];
__device__ __nv_bfloat16 g_wq[768 * 256];
__device__ __nv_bfloat16 g_wp[256 * 256];
__device__ __nv_bfloat16 g_w1[1024 * 256];
__device__ __nv_bfloat16 g_w2[256 * 1024];

// ---------------- helpers ----------------
__device__ __forceinline__ uint32_t smem_u32(const void* p) {
    uint32_t a;
    asm("{ .reg .u64 t; cvta.to.shared.u64 t, %1; cvt.u32.u64 %0, t; }"
        : "=r"(a) : "l"(p));
    return a;
}
__device__ __forceinline__ void cp16(uint32_t dst, const void* src) {
    asm volatile("cp.async.ca.shared.global [%0], [%1], 16;" :: "r"(dst), "l"(src));
}
#define CP_COMMIT() asm volatile("cp.async.commit_group;" ::: "memory")
#define CP_WAIT(n)  asm volatile("cp.async.wait_group %0;" :: "n"(n) : "memory")

__device__ __forceinline__ void mma_bf16(float d[4], uint32_t a0, uint32_t a1,
                                         uint32_t a2, uint32_t a3,
                                         uint32_t b0, uint32_t b1) {
    asm volatile(
        "mma.sync.aligned.m16n8k16.row.col.f32.bf16.bf16.f32 "
        "{%0,%1,%2,%3}, {%4,%5,%6,%7}, {%8,%9}, {%0,%1,%2,%3};"
        : "+f"(d[0]), "+f"(d[1]), "+f"(d[2]), "+f"(d[3])
        : "r"(a0), "r"(a1), "r"(a2), "r"(a3), "r"(b0), "r"(b1));
}
__device__ __forceinline__ void ldsm_x4(uint32_t& r0, uint32_t& r1,
                                        uint32_t& r2, uint32_t& r3, uint32_t a) {
    asm volatile("ldmatrix.sync.aligned.m8n8.x4.shared.b16 {%0,%1,%2,%3}, [%4];"
                 : "=r"(r0), "=r"(r1), "=r"(r2), "=r"(r3) : "r"(a));
}
__device__ __forceinline__ float bflo(uint32_t u) { return __uint_as_float(u << 16); }
__device__ __forceinline__ float bfhi(uint32_t u) { return __uint_as_float(u & 0xffff0000u); }

__device__ __forceinline__ float gelu_fast(float v) {
    float x3 = v * v * v;
    float u = 0.7978845608028654f * (v + 0.044715f * x3);
    float th;
    asm("tanh.approx.f32 %0, %1;" : "=f"(th) : "f"(u));
    return 0.5f * v * (1.f + th);
}

// ---------------- data -> bf16 mirror ----------------
__global__ void __launch_bounds__(256) convert_data_kernel(
    const float* __restrict__ data)
{
    int i = blockIdx.x * 256 + threadIdx.x;
    const float4* s = (const float4*)data + (size_t)i * 2;
    float4 a = s[0], b = s[1];
    __nv_bfloat162 p0 = __floats2bfloat162_rn(a.x, a.y);
    __nv_bfloat162 p1 = __floats2bfloat162_rn(a.z, a.w);
    __nv_bfloat162 p2 = __floats2bfloat162_rn(b.x, b.y);
    __nv_bfloat162 p3 = __floats2bfloat162_rn(b.z, b.w);
    uint4 o;
    o.x = *(uint32_t*)&p0; o.y = *(uint32_t*)&p1;
    o.z = *(uint32_t*)&p2; o.w = *(uint32_t*)&p3;
    ((uint4*)g_databf)[i] = o;
}

// ---------------- fused weight transpose -> bf16 (all four) ----------------
__global__ void transpose_all_kernel(
    const float* __restrict__ qkv_w, const float* __restrict__ proj_w,
    const float* __restrict__ fc1_w, const float* __restrict__ fc2_w)
{
    int i = blockIdx.x * 256 + threadIdx.x;
    if (i < 196608) {
        int n = i / 256, k = i - n * 256;
        g_wq[i] = __float2bfloat16(qkv_w[(size_t)k * 768 + n]);
    } else if (i < 262144) {
        int j = i - 196608;
        int n = j / 256, k = j - n * 256;
        g_wp[j] = __float2bfloat16(proj_w[(size_t)k * 256 + n]);
    } else if (i < 524288) {
        int j = i - 262144;
        int n = j / 256, k = j - n * 256;
        g_w1[j] = __float2bfloat16(fc1_w[(size_t)k * 1024 + n]);
    } else {
        int j = i - 524288;
        int n = j / 1024, k = j - n * 1024;
        g_w2[j] = __float2bfloat16(fc2_w[(size_t)k * 256 + n]);
    }
}

// ---------------- fused CPE + build x + LN1 (bf16 gather) ----------------
__global__ void __launch_bounds__(256) cpe_ln1_kernel(
    const float* __restrict__ data, const float* __restrict__ relay,
    const int* __restrict__ neigh, const float* __restrict__ cpe_w,
    const float* __restrict__ bn_gamma, const float* __restrict__ bn_beta,
    const float* __restrict__ bn_mean, const float* __restrict__ bn_var,
    const float* __restrict__ g, const float* __restrict__ b)
{
    int warp = threadIdx.x >> 5, lane = threadIdx.x & 31;
    int gr = blockIdx.x * 8 + warp;
    int w = gr / SDIM, s = gr - w * SDIM;

    float v[8];
    if (s == 0) {
        const float4* src = (const float4*)(relay + (size_t)w * CDIM) + lane * 2;
        float4 a = src[0], bb4 = src[1];
        v[0] = a.x; v[1] = a.y; v[2] = a.z; v[3] = a.w;
        v[4] = bb4.x; v[5] = bb4.y; v[6] = bb4.z; v[7] = bb4.w;
    } else {
        int n = w * KTOK + s - 1;
        int nb = (lane < KC) ? neigh[(size_t)n * KC + lane] : 0;
        float acc[8];
        #pragma unroll
        for (int i = 0; i < 8; i++) acc[i] = 0.f;
        #pragma unroll
        for (int k = 0; k < KC; k++) {
            int idx = __shfl_sync(0xffffffffu, nb, k);
            uint4 d4 = ((const uint4*)g_databf)[(size_t)idx * 32 + lane];
            const float4* wr = (const float4*)(cpe_w + k * CDIM) + lane * 2;
            float4 w0 = wr[0], w1 = wr[1];
            acc[0] = fmaf(bflo(d4.x), w0.x, acc[0]);
            acc[1] = fmaf(bfhi(d4.x), w0.y, acc[1]);
            acc[2] = fmaf(bflo(d4.y), w0.z, acc[2]);
            acc[3] = fmaf(bfhi(d4.y), w0.w, acc[3]);
            acc[4] = fmaf(bflo(d4.z), w1.x, acc[4]);
            acc[5] = fmaf(bfhi(d4.z), w1.y, acc[5]);
            acc[6] = fmaf(bflo(d4.w), w1.z, acc[6]);
            acc[7] = fmaf(bfhi(d4.w), w1.w, acc[7]);
        }
        const float4* dr = (const float4*)(data + (size_t)n * CDIM) + lane * 2;
        const float4* bm = (const float4*)bn_mean + lane * 2;
        const float4* bv = (const float4*)bn_var + lane * 2;
        const float4* bg = (const float4*)bn_gamma + lane * 2;
        const float4* bb = (const float4*)bn_beta + lane * 2;
        #pragma unroll
        for (int i = 0; i < 2; i++) {
            float4 d = dr[i], m = bm[i], va = bv[i], ga = bg[i], be = bb[i];
            v[4*i]   = d.x + (acc[4*i]   - m.x) * rsqrtf(va.x + EPS) * ga.x + be.x;
            v[4*i+1] = d.y + (acc[4*i+1] - m.y) * rsqrtf(va.y + EPS) * ga.y + be.y;
            v[4*i+2] = d.z + (acc[4*i+2] - m.z) * rsqrtf(va.z + EPS) * ga.z + be.z;
            v[4*i+3] = d.w + (acc[4*i+3] - m.w) * rsqrtf(va.w + EPS) * ga.w + be.w;
        }
    }

    float sm = 0.f, s2 = 0.f;
    #pragma unroll
    for (int i = 0; i < 8; i++) { sm += v[i]; s2 = fmaf(v[i], v[i], s2); }
    #pragma unroll
    for (int o = 16; o; o >>= 1) {
        sm += __shfl_xor_sync(0xffffffffu, sm, o);
        s2 += __shfl_xor_sync(0xffffffffu, s2, o);
    }
    float mu = sm * (1.f / CDIM);
    float rs = rsqrtf(s2 * (1.f / CDIM) - mu * mu + EPS);

    float4* xo = (float4*)(g_x + (size_t)gr * CDIM) + lane * 2;
    xo[0] = make_float4(v[0], v[1], v[2], v[3]);
    xo[1] = make_float4(v[4], v[5], v[6], v[7]);

    const float4* gg = (const float4*)g + lane * 2;
    const float4* gb = (const float4*)b + lane * 2;
    float hh[8];
    #pragma unroll
    for (int i = 0; i < 2; i++) {
        float4 ga = gg[i], be = gb[i];
        hh[4*i]   = (v[4*i]   - mu) * rs * ga.x + be.x;
        hh[4*i+1] = (v[4*i+1] - mu) * rs * ga.y + be.y;
        hh[4*i+2] = (v[4*i+2] - mu) * rs * ga.z + be.z;
        hh[4*i+3] = (v[4*i+3] - mu) * rs * ga.w + be.w;
    }
    __nv_bfloat162 p0 = __floats2bfloat162_rn(hh[0], hh[1]);
    __nv_bfloat162 p1 = __floats2bfloat162_rn(hh[2], hh[3]);
    __nv_bfloat162 p2 = __floats2bfloat162_rn(hh[4], hh[5]);
    __nv_bfloat162 p3 = __floats2bfloat162_rn(hh[6], hh[7]);
    uint4 ho;
    ho.x = *(uint32_t*)&p0; ho.y = *(uint32_t*)&p1;
    ho.z = *(uint32_t*)&p2; ho.w = *(uint32_t*)&p3;
    ((uint4*)(g_h + (size_t)gr * CDIM))[lane] = ho;
}

// ---------------- LN2: g_x2 (fp32) -> g_h2 (bf16) ----------------
__global__ void __launch_bounds__(256) ln2_kernel(
    const float* __restrict__ g, const float* __restrict__ b)
{
    int warp = threadIdx.x >> 5, lane = threadIdx.x & 31;
    int gr = blockIdx.x * 8 + warp;
    const float2* src = (const float2*)(g_x2 + (size_t)gr * CDIM);
    float2 v[4];
    float sm = 0.f, s2 = 0.f;
    #pragma unroll
    for (int i = 0; i < 4; i++) {
        v[i] = src[lane + i * 32];
        sm += v[i].x + v[i].y;
        s2 = fmaf(v[i].x, v[i].x, fmaf(v[i].y, v[i].y, s2));
    }
    #pragma unroll
    for (int o = 16; o; o >>= 1) {
        sm += __shfl_xor_sync(0xffffffffu, sm, o);
        s2 += __shfl_xor_sync(0xffffffffu, s2, o);
    }
    float mu = sm * (1.f / CDIM);
    float rs = rsqrtf(s2 * (1.f / CDIM) - mu * mu + EPS);
    uint32_t* ho = (uint32_t*)(g_h2 + (size_t)gr * CDIM);
    const float2* gg = (const float2*)g;
    const float2* gb = (const float2*)b;
    #pragma unroll
    for (int i = 0; i < 4; i++) {
        int c = lane + i * 32;
        float2 ga = gg[c], be = gb[c];
        __nv_bfloat162 h = __floats2bfloat162_rn(
            (v[i].x - mu) * rs * ga.x + be.x,
            (v[i].y - mu) * rs * ga.y + be.y);
        ho[c] = *(uint32_t*)&h;
    }
}

// ---------------- attention v7: 2 threads per (head, query) ----------------
#define KVU 264
#define ATTN_SMEM (SDIM * KVU * 4)

__global__ void __launch_bounds__(544, 2) attn_kernel()
{
    extern __shared__ uint32_t skv[];
    int w = blockIdx.x, tid = threadIdx.x;

    const uint4* src4 = (const uint4*)(g_qkv + (size_t)w * SDIM * 768);
    for (int i = tid; i < SDIM * 64; i += 544) {
        int r = i >> 6, c = i & 63;
        uint4 q4 = src4[r * 96 + 32 + c];
        *(uint4*)(skv + r * KVU + c * 4) = q4;
    }
    __syncthreads();

    int p = tid >> 1, half = tid & 1;
    int h = p / SDIM;
    int s = p - h * SDIM;
    if (h > 7) { h = 7; }
    const float scale = 0.17677669529663687f;
    const int doff = h * 16 + half * 8;

    float q[16];
    {
        const uint32_t* qsrc = (const uint32_t*)(
            g_qkv + ((size_t)w * SDIM + (s < SDIM ? s : 0)) * 768) + doff;
        #pragma unroll
        for (int i = 0; i < 8; i++) {
            uint32_t pq = qsrc[i];
            q[2 * i]     = bflo(pq) * scale;
            q[2 * i + 1] = bfhi(pq) * scale;
        }
    }

    float o[16];
    #pragma unroll
    for (int d = 0; d < 16; d++) o[d] = 0.f;
    float ssum = 0.f;

    #pragma unroll 1
    for (int t = 0; t < SDIM; t++) {
        const uint4* kr = (const uint4*)(skv + t * KVU + doff);
        uint4 k0 = kr[0], k1 = kr[1];
        float d0 = 0.f, d1 = 0.f, d2 = 0.f, d3 = 0.f;
        d0 = fmaf(q[0],  bflo(k0.x), d0);
        d1 = fmaf(q[1],  bfhi(k0.x), d1);
        d2 = fmaf(q[2],  bflo(k0.y), d2);
        d3 = fmaf(q[3],  bfhi(k0.y), d3);
        d0 = fmaf(q[4],  bflo(k0.z), d0);
        d1 = fmaf(q[5],  bfhi(k0.z), d1);
        d2 = fmaf(q[6],  bflo(k0.w), d2);
        d3 = fmaf(q[7],  bfhi(k0.w), d3);
        d0 = fmaf(q[8],  bflo(k1.x), d0);
        d1 = fmaf(q[9],  bfhi(k1.x), d1);
        d2 = fmaf(q[10], bflo(k1.y), d2);
        d3 = fmaf(q[11], bfhi(k1.y), d3);
        d0 = fmaf(q[12], bflo(k1.z), d0);
        d1 = fmaf(q[13], bfhi(k1.z), d1);
        d2 = fmaf(q[14], bflo(k1.w), d2);
        d3 = fmaf(q[15], bfhi(k1.w), d3);
        float dhalf = (d0 + d1) + (d2 + d3);
        float dot = dhalf + __shfl_xor_sync(0xffffffffu, dhalf, 1);
        float e = __expf(dot);
        ssum += e;

        const uint4* vr = (const uint4*)(skv + t * KVU + 128 + doff);
        uint4 v0 = vr[0], v1 = vr[1];
        o[0]  = fmaf(e, bflo(v0.x), o[0]);
        o[1]  = fmaf(e, bfhi(v0.x), o[1]);
        o[2]  = fmaf(e, bflo(v0.y), o[2]);
        o[3]  = fmaf(e, bfhi(v0.y), o[3]);
        o[4]  = fmaf(e, bflo(v0.z), o[4]);
        o[5]  = fmaf(e, bfhi(v0.z), o[5]);
        o[6]  = fmaf(e, bflo(v0.w), o[6]);
        o[7]  = fmaf(e, bfhi(v0.w), o[7]);
        o[8]  = fmaf(e, bflo(v1.x), o[8]);
        o[9]  = fmaf(e, bfhi(v1.x), o[9]);
        o[10] = fmaf(e, bflo(v1.y), o[10]);
        o[11] = fmaf(e, bfhi(v1.y), o[11]);
        o[12] = fmaf(e, bflo(v1.z), o[12]);
        o[13] = fmaf(e, bfhi(v1.z), o[13]);
        o[14] = fmaf(e, bflo(v1.w), o[14]);
        o[15] = fmaf(e, bfhi(v1.w), o[15]);
    }

    if (tid < HEADS * SDIM * 2) {
        float inv = 1.f / ssum;
        uint32_t pk[8];
        #pragma unroll
        for (int i = 0; i < 8; i++) {
            __nv_bfloat162 pp = __floats2bfloat162_rn(o[2*i] * inv, o[2*i+1] * inv);
            pk[i] = *(uint32_t*)&pp;
        }
        uint4* dst = (uint4*)((uint32_t*)(
            g_attn + ((size_t)w * SDIM + s) * CDIM + h * DHEAD) + half * 8);
        dst[0] = make_uint4(pk[0], pk[1], pk[2], pk[3]);
        dst[1] = make_uint4(pk[4], pk[5], pk[6], pk[7]);
    }
}

// ---------------- bf16 mma.sync GEMM (pipelined fragments) ----------------
#define CHUNK_K 64
#define SBF     72
#define SBF_B   (SBF * 2)
#define BUF_ELE (256 * SBF)
#define BUF_BYTES (BUF_ELE * 2)
#define GEMM_SMEM (2 * BUF_BYTES)
#define STW 68

template<int KT, int NT, int EPI>
__global__ void __launch_bounds__(256, 2) gemm_mma(
    const __nv_bfloat16* __restrict__ A, const __nv_bfloat16* __restrict__ B,
    const float* __restrict__ bias, const float* __restrict__ res,
    void* __restrict__ outp)
{
    extern __shared__ float smemf[];
    __nv_bfloat16* smem = (__nv_bfloat16*)smemf;
    const int tid = threadIdx.x;
    const int wid = tid >> 5, lane = tid & 31;
    const int g = lane >> 2, t = lane & 3;
    const int warp_m = wid & 1, warp_n = wid >> 1;
    const int n0 = blockIdx.x * 128;
    const int m0 = blockIdx.y * 128;
    const uint32_t sbase = smem_u32(smem);

    const int lm = lane >> 3;
    const int lr = lane & 7;
    const uint32_t a_off0 = (uint32_t)(warp_m * 64 + (lm & 1) * 8 + lr) * SBF_B
                          + (uint32_t)(lm >> 1) * 16;
    const uint32_t b_off0 = (uint32_t)(128 * SBF_B)
                          + (uint32_t)(warp_n * 32 + (lm >> 1) * 8 + lr) * SBF_B
                          + (uint32_t)(lm & 1) * 16;

    float acc[4][4][4];
    #pragma unroll
    for (int i = 0; i < 4; i++)
        #pragma unroll
        for (int j = 0; j < 4; j++)
            #pragma unroll
            for (int r = 0; r < 4; r++) acc[i][j][r] = 0.f;

    constexpr int KCH = KT / CHUNK_K;

    auto load_chunk = [&](int s, int kc) {
        uint32_t base = sbase + (uint32_t)s * BUF_BYTES;
        #pragma unroll
        for (int it = 0; it < 4; it++) {
            int idx = it * 256 + tid;
            int row = idx >> 3, seg = idx & 7;
            cp16(base + (uint32_t)(row * SBF_B + seg * 16),
                 A + (size_t)(m0 + row) * KT + kc * CHUNK_K + seg * 8);
        }
        #pragma unroll
        for (int it = 0; it < 4; it++) {
            int idx = it * 256 + tid;
            int row = idx >> 3, seg = idx & 7;
            cp16(base + (uint32_t)(128 * SBF_B + row * SBF_B + seg * 16),
                 B + (size_t)(n0 + row) * KT + kc * CHUNK_K + seg * 8);
        }
    };

    load_chunk(0, 0); CP_COMMIT();

    for (int kc = 0; kc < KCH; kc++) {
        int s = kc & 1;
        if (kc + 1 < KCH) {
            load_chunk((kc + 1) & 1, kc + 1); CP_COMMIT();
            CP_WAIT(1);
        } else {
            CP_WAIT(0);
        }
        __syncthreads();

        uint32_t abase = sbase + (uint32_t)s * BUF_BYTES + a_off0;
        uint32_t bbase = sbase + (uint32_t)s * BUF_BYTES + b_off0;

        // software-pipelined fragments: af double-buffered per (ks,mt) step,
        // bf double-buffered per ks parity, prefetched one step ahead.
        uint32_t af[2][4];
        uint32_t bf[2][4][2];
        ldsm_x4(bf[0][0][0], bf[0][0][1], bf[0][1][0], bf[0][1][1], bbase);
        ldsm_x4(bf[0][2][0], bf[0][2][1], bf[0][3][0], bf[0][3][1],
                bbase + 16u * SBF_B);
        ldsm_x4(af[0][0], af[0][1], af[0][2], af[0][3], abase);

        #pragma unroll
        for (int idx = 0; idx < 16; idx++) {
            const int ks = idx >> 2, mt = idx & 3;
            const int cur = idx & 1, kpar = ks & 1;
            if (idx < 15) {
                const int ks2 = (idx + 1) >> 2, mt2 = (idx + 1) & 3;
                if (mt2 == 0) {
                    uint32_t kb2 = (uint32_t)ks2 * 32;
                    ldsm_x4(bf[ks2 & 1][0][0], bf[ks2 & 1][0][1],
                            bf[ks2 & 1][1][0], bf[ks2 & 1][1][1], bbase + kb2);
                    ldsm_x4(bf[ks2 & 1][2][0], bf[ks2 & 1][2][1],
                            bf[ks2 & 1][3][0], bf[ks2 & 1][3][1],
                            bbase + kb2 + 16u * SBF_B);
                }
                ldsm_x4(af[1 - cur][0], af[1 - cur][1],
                        af[1 - cur][2], af[1 - cur][3],
                        abase + (uint32_t)ks2 * 32 + (uint32_t)mt2 * 16u * SBF_B);
            }
            #pragma unroll
            for (int nt = 0; nt < 4; nt++)
                mma_bf16(acc[mt][nt], af[cur][0], af[cur][1],
                         af[cur][2], af[cur][3],
                         bf[kpar][nt][0], bf[kpar][nt][1]);
        }
        __syncthreads();
    }

    if (EPI == 0 || EPI == 2) {
        uint32_t* stg16 = (uint32_t*)smemf;
        float bcol[4][2];
        #pragma unroll
        for (int nt = 0; nt < 4; nt++) {
            int col = warp_n * 32 + nt * 8 + 2 * t;
            bcol[nt][0] = bias[n0 + col];
            bcol[nt][1] = bias[n0 + col + 1];
        }
        #pragma unroll
        for (int mt = 0; mt < 4; mt++) {
            int row = warp_m * 64 + mt * 16 + g;
            #pragma unroll
            for (int nt = 0; nt < 4; nt++) {
                int colw = (warp_n * 32 + nt * 8 + 2 * t) >> 1;
                float v0 = acc[mt][nt][0] + bcol[nt][0];
                float v1 = acc[mt][nt][1] + bcol[nt][1];
                float v2 = acc[mt][nt][2] + bcol[nt][0];
                float v3 = acc[mt][nt][3] + bcol[nt][1];
                if (EPI == 2) {
                    v0 = gelu_fast(v0); v1 = gelu_fast(v1);
                    v2 = gelu_fast(v2); v3 = gelu_fast(v3);
                }
                __nv_bfloat162 p0 = __floats2bfloat162_rn(v0, v1);
                __nv_bfloat162 p1 = __floats2bfloat162_rn(v2, v3);
                stg16[row * STW + colw]       = *(uint32_t*)&p0;
                stg16[(row + 8) * STW + colw] = *(uint32_t*)&p1;
            }
        }
        __syncthreads();
        uint4* ob4 = (uint4*)outp;
        #pragma unroll
        for (int it = 0; it < 8; it++) {
            int i = it * 256 + tid;
            int row = i >> 4, seg = i & 15;
            uint4 val = *(uint4*)(stg16 + row * STW + seg * 4);
            ob4[((size_t)(m0 + row) * NT + n0) / 8 + seg] = val;
        }
    } else {
        float* stg = smemf;
        #pragma unroll
        for (int mt = 0; mt < 4; mt++) {
            #pragma unroll
            for (int nt = 0; nt < 4; nt++) {
                int row = warp_m * 64 + mt * 16 + g;
                int col = warp_n * 32 + nt * 8 + 2 * t;
                stg[row * 132 + col]           = acc[mt][nt][0];
                stg[row * 132 + col + 1]       = acc[mt][nt][1];
                stg[(row + 8) * 132 + col]     = acc[mt][nt][2];
                stg[(row + 8) * 132 + col + 1] = acc[mt][nt][3];
            }
        }
        __syncthreads();

        int col = tid & 127;
        int r0  = tid >> 7;
        float bi = bias[n0 + col];
        float* of = (float*)outp;
        #pragma unroll 4
        for (int i = 0; i < 64; i++) {
            int r = r0 + i * 2;
            int gr = m0 + r;
            float v = stg[r * 132 + col] + bi + res[(size_t)gr * NT + n0 + col];
            if (EPI == 3) {
                int w = gr / SDIM, sx = gr - (gr / SDIM) * SDIM;
                size_t dst = (sx == 0)
                    ? ((size_t)NTOK * CDIM + (size_t)w * CDIM + n0 + col)
                    : (((size_t)(w * KTOK + sx - 1)) * CDIM + n0 + col);
                of[dst] = v;
            } else {
                of[(size_t)gr * NT + n0 + col] = v;
            }
        }
    }
}

// ---------------------------------------------------------------------------
extern "C" void kernel_launch(void* const* d_in, const int* in_sizes, int n_in,
                              void* d_out, int out_size)
{
    const float* data     = (const float*)d_in[0];
    const float* relay    = (const float*)d_in[1];
    const int*   neigh    = (const int*)  d_in[2];
    const float* cpe_w    = (const float*)d_in[3];
    const float* bn_gamma = (const float*)d_in[4];
    const float* bn_beta  = (const float*)d_in[5];
    const float* bn_mean  = (const float*)d_in[6];
    const float* bn_var   = (const float*)d_in[7];
    const float* norm1_g  = (const float*)d_in[8];
    const float* norm1_b  = (const float*)d_in[9];
    const float* qkv_w    = (const float*)d_in[10];
    const float* qkv_b    = (const float*)d_in[11];
    const float* proj_w   = (const float*)d_in[12];
    const float* proj_b   = (const float*)d_in[13];
    const float* norm2_g  = (const float*)d_in[14];
    const float* norm2_b  = (const float*)d_in[15];
    const float* fc1_w    = (const float*)d_in[16];
    const float* fc1_b    = (const float*)d_in[17];
    const float* fc2_w    = (const float*)d_in[18];
    const float* fc2_b    = (const float*)d_in[19];
    float* out = (float*)d_out;

    static bool inited = false;
    static __nv_bfloat16 *p_h, *p_h2, *p_qkv, *p_attn, *p_f1;
    static __nv_bfloat16 *p_wq, *p_wp, *p_w1, *p_w2;
    static float *p_x, *p_x2;
    if (!inited) {
        cudaFuncSetAttribute(gemm_mma<256, 768, 0>,
            cudaFuncAttributeMaxDynamicSharedMemorySize, GEMM_SMEM);
        cudaFuncSetAttribute(gemm_mma<256, 256, 1>,
            cudaFuncAttributeMaxDynamicSharedMemorySize, GEMM_SMEM);
        cudaFuncSetAttribute(gemm_mma<256, 1024, 2>,
            cudaFuncAttributeMaxDynamicSharedMemorySize, GEMM_SMEM);
        cudaFuncSetAttribute(gemm_mma<1024, 256, 3>,
            cudaFuncAttributeMaxDynamicSharedMemorySize, GEMM_SMEM);
        cudaFuncSetAttribute(attn_kernel,
            cudaFuncAttributeMaxDynamicSharedMemorySize, ATTN_SMEM);
        void* t;
        cudaGetSymbolAddress(&t, g_h);    p_h    = (__nv_bfloat16*)t;
        cudaGetSymbolAddress(&t, g_h2);   p_h2   = (__nv_bfloat16*)t;
        cudaGetSymbolAddress(&t, g_qkv);  p_qkv  = (__nv_bfloat16*)t;
        cudaGetSymbolAddress(&t, g_attn); p_attn = (__nv_bfloat16*)t;
        cudaGetSymbolAddress(&t, g_f1);   p_f1   = (__nv_bfloat16*)t;
        cudaGetSymbolAddress(&t, g_x);    p_x    = (float*)t;
        cudaGetSymbolAddress(&t, g_x2);   p_x2   = (float*)t;
        cudaGetSymbolAddress(&t, g_wq);   p_wq   = (__nv_bfloat16*)t;
        cudaGetSymbolAddress(&t, g_wp);   p_wp   = (__nv_bfloat16*)t;
        cudaGetSymbolAddress(&t, g_w1);   p_w1   = (__nv_bfloat16*)t;
        cudaGetSymbolAddress(&t, g_w2);   p_w2   = (__nv_bfloat16*)t;
        inited = true;
    }

    convert_data_kernel<<<NTOK * CDIM / 8 / 256, 256>>>(data);
    transpose_all_kernel<<<786432 / 256, 256>>>(qkv_w, proj_w, fc1_w, fc2_w);

    cpe_ln1_kernel<<<RTOT / 8, 256>>>(data, relay, neigh, cpe_w,
                                      bn_gamma, bn_beta, bn_mean, bn_var,
                                      norm1_g, norm1_b);

    const int GB = RTOT / 128;  // 1056
    gemm_mma<256, 768, 0><<<dim3(6, GB), 256, GEMM_SMEM>>>(p_h, p_wq, qkv_b, nullptr, p_qkv);

    attn_kernel<<<W_WIN, 544, ATTN_SMEM>>>();

    gemm_mma<256, 256, 1><<<dim3(2, GB), 256, GEMM_SMEM>>>(p_attn, p_wp, proj_b, p_x, p_x2);

    ln2_kernel<<<RTOT / 8, 256>>>(norm2_g, norm2_b);

    gemm_mma<256, 1024, 2><<<dim3(8, GB), 256, GEMM_SMEM>>>(p_h2, p_w1, fc1_b, nullptr, p_f1);

    gemm_mma<1024, 256, 3><<<dim3(2, GB), 256, GEMM_SMEM>>>(p_f1, p_w2, fc2_b, p_x2, out);
}